// round 14
// baseline (speedup 1.0000x reference)
#include <cuda_runtime.h>
#include <math.h>
#include <stdint.h>

#define EPSLN 1e-5f
#define DT    0.01f
#define CDIM  256
#define BDIM  8
#define NTOK  256
#define HEADS 8
#define HD    32
#define ROWS  (BDIM * NTOK)

// ---- ODE smem layout (bytes): 32 rows/CTA ----
#define OFF_AST  0          // 16384 (bf16 A-stage, 32 rows)
#define OFF_W1R  16384      // 131072 (W1 resident)
#define OFF_W20  147456     // 16384
#define OFF_W21  163840     // 16384
#define OFF_W22  180224     // 16384
#define OFF_RED  196608     // 2048
#define OFF_STAT 198656     // 512
#define OFF_CST  199168     // 4096
#define ODE_SMEM 203264

// ---- prologue mma kernels smem layout (bytes) ----
#define P_AST    0          // 16 KB tf32 A-stage
#define P_W0     16384      // 32 KB
#define P_W1     49152      // 32 KB
#define P_RED    81920      // 256 floats
#define P_STAT   82944      // 32 floats
#define QKV_SMEM 81920
#define PROJ_SMEM 83072

// ---------------------------------------------------------------------------
// Scratch globals
// ---------------------------------------------------------------------------
__device__ float g_qbuf[3 * BDIM * HEADS * NTOK * HD];
__device__ float g_attnout[ROWS * CDIM];
__device__ float g_x1[ROWS * CDIM];
__device__ float g_ys[ROWS * CDIM];
__device__ float g_arg[ROWS * CDIM];
__device__ float g_k1[ROWS * CDIM];
__device__ float g_k2[ROWS * CDIM];
__device__ float g_k3[ROWS * CDIM];
// bf16-pair ODE weights in MMA-B layout
__device__ uint32_t g_wt1[CDIM * CDIM / 2];
__device__ uint32_t g_wt2[CDIM * CDIM / 2];
// tf32 MMA-B layout prologue weights
__device__ float g_wqkv_t[CDIM * 768];
__device__ float g_wo_t[CDIM * CDIM];

// ---------------------------------------------------------------------------
// helpers
// ---------------------------------------------------------------------------
__device__ __forceinline__ uint32_t f2bf2(float lo, float hi) {
    uint32_t r; asm("cvt.rn.bf16x2.f32 %0, %1, %2;" : "=r"(r) : "f"(hi), "f"(lo)); return r;
}
__device__ __forceinline__ uint32_t f2tf(float f) {
    uint32_t r; asm("cvt.rna.tf32.f32 %0, %1;" : "=r"(r) : "f"(f)); return r;
}
__device__ __forceinline__ void lds2u(uint32_t a, uint32_t& x, uint32_t& y) {
    asm volatile("ld.shared.v2.b32 {%0,%1}, [%2];" : "=r"(x), "=r"(y) : "r"(a));
}
__device__ __forceinline__ void sts1u(uint32_t a, uint32_t v) {
    asm volatile("st.shared.b32 [%0], %1;" :: "r"(a), "r"(v));
}
__device__ __forceinline__ void cp_async16(uint32_t sdst, const void* gsrc) {
    asm volatile("cp.async.cg.shared.global [%0], [%1], 16;" :: "r"(sdst), "l"(gsrc));
}
__device__ __forceinline__ void cp_commit() { asm volatile("cp.async.commit_group;"); }
__device__ __forceinline__ void cp_wait1() { asm volatile("cp.async.wait_group 1;" ::: "memory"); }
__device__ __forceinline__ void cp_wait0() { asm volatile("cp.async.wait_group 0;" ::: "memory"); }

__device__ __forceinline__ void mma_bf(float& c0, float& c1, float& c2, float& c3,
                                       uint32_t a0, uint32_t a1, uint32_t a2, uint32_t a3,
                                       uint32_t b0, uint32_t b1) {
    asm volatile(
        "mma.sync.aligned.m16n8k16.row.col.f32.bf16.bf16.f32 "
        "{%0,%1,%2,%3},{%4,%5,%6,%7},{%8,%9},{%0,%1,%2,%3};"
        : "+f"(c0), "+f"(c1), "+f"(c2), "+f"(c3)
        : "r"(a0), "r"(a1), "r"(a2), "r"(a3), "r"(b0), "r"(b1));
}
__device__ __forceinline__ void mma_tf(float& c0, float& c1, float& c2, float& c3,
                                       uint32_t a0, uint32_t a1, uint32_t a2, uint32_t a3,
                                       uint32_t b0, uint32_t b1) {
    asm volatile(
        "mma.sync.aligned.m16n8k8.row.col.f32.tf32.tf32.f32 "
        "{%0,%1,%2,%3},{%4,%5,%6,%7},{%8,%9},{%0,%1,%2,%3};"
        : "+f"(c0), "+f"(c1), "+f"(c2), "+f"(c3)
        : "r"(a0), "r"(a1), "r"(a2), "r"(a3), "r"(b0), "r"(b1));
}

// bf16 A-stage byte offset (ODE, 32 rows: chunk stride 1024)
__device__ __forceinline__ uint32_t astb3(int r, int cb) {
    int pc = (cb >> 1) & 7;
    return OFF_AST + (uint32_t)((cb >> 4) * 1024 + r * 32 + ((pc & 3) * 2 + (pc >> 2)) * 4);
}
// tf32 A-stage byte offset (prologue)
__device__ __forceinline__ uint32_t astf(int r, int c) {
    return P_AST + (uint32_t)((c >> 3) * 512 + r * 32 + (c & 3) * 8 + ((c >> 2) & 1) * 4);
}

// ---------------------------------------------------------------------------
// prep kernels
// ---------------------------------------------------------------------------
__global__ void prep_w_kernel(const float* __restrict__ wl1, const float* __restrict__ wl2) {
    int idx = blockIdx.x * 256 + threadIdx.x;
    int kp = idx >> 8, n = idx & 255;
    int k = kp * 2;
    int pc = kp & 7;
    int dst = (k >> 5) * 4096 + ((k >> 4) & 1) * 2048 + n * 8 + (pc & 3) * 2 + (pc >> 2);
    g_wt1[dst] = f2bf2(wl1[k * 256 + n], wl1[(k + 1) * 256 + n]);
    g_wt2[dst] = f2bf2(wl2[k * 256 + n], wl2[(k + 1) * 256 + n]);
}
__global__ void prep_qkv_kernel(const float* __restrict__ wqkv) {
    int k = blockIdx.x, n = threadIdx.x, g = blockIdx.y;
    int dst = g * 65536 + (k >> 5) * 8192 + ((k >> 3) & 3) * 2048 + n * 8 + (k & 3) * 2 + ((k >> 2) & 1);
    g_wqkv_t[dst] = __uint_as_float(f2tf(wqkv[k * 768 + g * 256 + n]));
}
__global__ void prep_wo_kernel(const float* __restrict__ wo) {
    int k = blockIdx.x, n = threadIdx.x;
    int dst = (k >> 5) * 8192 + ((k >> 3) & 3) * 2048 + n * 8 + (k & 3) * 2 + ((k >> 2) & 1);
    g_wo_t[dst] = __uint_as_float(f2tf(wo[k * 256 + n]));
}

// ---------------------------------------------------------------------------
// prologue tf32 GEMM core
// ---------------------------------------------------------------------------
__device__ __forceinline__ void prefB32(uint32_t sdst, const float* gsrc, int tid) {
#pragma unroll
    for (int i = 0; i < 8; i++) {
        int off = (tid + i * 256) * 16;
        cp_async16(sdst + off, (const char*)gsrc + off);
    }
    cp_commit();
}

__device__ __forceinline__ void run_gemm_tf(uint32_t sbase, const float* gw,
                                            float acc[4][4], int warp, int lane, int tid) {
    int quad = lane >> 2, q = lane & 3;
#pragma unroll
    for (int t = 0; t < 4; t++)
#pragma unroll
        for (int j = 0; j < 4; j++) acc[t][j] = 0.f;
    uint32_t aBase = sbase + P_AST + (uint32_t)(quad * 32 + q * 8);
    uint32_t bBase = (uint32_t)(warp * 1024 + quad * 32 + q * 8);
    for (int p = 0; p < 8; p++) {
        if (p < 7) {
            prefB32(sbase + (((p + 1) & 1) ? P_W1 : P_W0), gw + (p + 1) * 8192, tid);
            cp_wait1();
        } else {
            cp_wait0();
        }
        __syncthreads();
        uint32_t wb = sbase + ((p & 1) ? P_W1 : P_W0) + bBase;
#pragma unroll
        for (int kc4 = 0; kc4 < 4; kc4++) {
            int kcg = p * 4 + kc4;
            uint32_t a0, a1, a2, a3;
            lds2u(aBase + kcg * 512, a0, a2);
            lds2u(aBase + kcg * 512 + 256, a1, a3);
            uint32_t bb = wb + kc4 * 8192;
#pragma unroll
            for (int t = 0; t < 4; t++) {
                uint32_t b0, b1;
                lds2u(bb + t * 256, b0, b1);
                mma_tf(acc[t][0], acc[t][1], acc[t][2], acc[t][3], a0, a1, a2, a3, b0, b1);
            }
        }
    }
}

// ---------------------------------------------------------------------------
// K1: qkv via tf32 mma
// ---------------------------------------------------------------------------
__global__ void __launch_bounds__(256, 1)
qkv_mma_kernel(const float* __restrict__ x, const float* __restrict__ bqkv) {
    extern __shared__ __align__(16) float smF[];
    uint32_t sbase;
    asm("{ .reg .u64 t; cvta.to.shared.u64 t, %1; cvt.u32.u64 %0, t; }"
        : "=r"(sbase) : "l"((const void*)smF));
    int tid = threadIdx.x, warp = tid >> 5, lane = tid & 31;
    int r0 = blockIdx.x * 16, g = blockIdx.y;

    for (int idx = tid; idx < 16 * 256; idx += 256) {
        int r = idx >> 8, c = idx & 255;
        sts1u(sbase + astf(r, c), f2tf(x[(r0 + r) * 256 + c]));
    }
    prefB32(sbase + P_W0, g_wqkv_t + g * 65536, tid);

    float acc[4][4];
    run_gemm_tf(sbase, g_wqkv_t + g * 65536, acc, warp, lane, tid);

    int quad = lane >> 2, q = lane & 3;
#pragma unroll
    for (int t = 0; t < 4; t++) {
        int cb = warp * 32 + t * 8 + q * 2;
        float2 bias = *(const float2*)(bqkv + g * 256 + cb);
        int h = cb >> 5, d = cb & 31;
#pragma unroll
        for (int half = 0; half < 2; half++) {
            int r = r0 + quad + half * 8;
            int b = r >> 8, n = r & 255;
            float2 ov;
            ov.x = acc[t][2 * half + 0] + bias.x;
            ov.y = acc[t][2 * half + 1] + bias.y;
            *(float2*)(g_qbuf + (((g * BDIM + b) * HEADS + h) * NTOK + n) * HD + d) = ov;
        }
    }
}

// ---------------------------------------------------------------------------
// K2: attention — split over query halves (128 CTAs)
// ---------------------------------------------------------------------------
#define ATTN_SMEM ((3 * 256 * 33 + 8 * 256) * 4)
__global__ void attn_kernel() {
    extern __shared__ float sm[];
    float* qs = sm;
    float* ks = qs + 256 * 33;
    float* vs = ks + 256 * 33;
    float* prob = vs + 256 * 33;
    int tid = threadIdx.x, lane = tid & 31, w = tid >> 5;
    int bh = blockIdx.x >> 1, half = blockIdx.x & 1;
    int b = bh >> 3, h = bh & 7;
    const float scale = 0.17677669529663687f;
    const float* qg = g_qbuf + ((0 * BDIM + b) * HEADS + h) * NTOK * HD;
    const float* kg = g_qbuf + ((1 * BDIM + b) * HEADS + h) * NTOK * HD;
    const float* vg = g_qbuf + ((2 * BDIM + b) * HEADS + h) * NTOK * HD;
    for (int idx = tid; idx < NTOK * HD; idx += 256) {
        int n = idx >> 5, d = idx & 31;
        qs[n * 33 + d] = qg[idx] * scale;
        ks[n * 33 + d] = kg[idx];
        vs[n * 33 + d] = vg[idx];
    }
    __syncthreads();
    for (int n = 128 * half + w; n < 128 * (half + 1); n += 8) {
        float s[8];
#pragma unroll
        for (int u = 0; u < 8; u++) {
            int j = lane + 32 * u;
            float a = 0.f;
#pragma unroll 8
            for (int d = 0; d < HD; d++) a = fmaf(qs[n * 33 + d], ks[j * 33 + d], a);
            s[u] = a;
        }
        float mx = s[0];
#pragma unroll
        for (int u = 1; u < 8; u++) mx = fmaxf(mx, s[u]);
#pragma unroll
        for (int o = 16; o > 0; o >>= 1) mx = fmaxf(mx, __shfl_xor_sync(0xffffffffu, mx, o));
        float sum = 0.f;
#pragma unroll
        for (int u = 0; u < 8; u++) { s[u] = __expf(s[u] - mx); sum += s[u]; }
#pragma unroll
        for (int o = 16; o > 0; o >>= 1) sum += __shfl_xor_sync(0xffffffffu, sum, o);
        float inv = 1.f / sum;
#pragma unroll
        for (int u = 0; u < 8; u++) prob[w * 256 + lane + 32 * u] = s[u] * inv;
        __syncwarp();
        float acc = 0.f;
#pragma unroll 8
        for (int j = 0; j < NTOK; j++) acc = fmaf(prob[w * 256 + j], vs[j * 33 + lane], acc);
        g_attnout[(b * NTOK + n) * CDIM + h * HD + lane] = acc;
        __syncwarp();
    }
}

// ---------------------------------------------------------------------------
// K3: x1 = LN(x + attnout @ wo + bo) via tf32 mma
// ---------------------------------------------------------------------------
__global__ void __launch_bounds__(256, 1)
proj_mma_kernel(const float* __restrict__ x, const float* __restrict__ bo,
                const float* __restrict__ g1, const float* __restrict__ b1) {
    extern __shared__ __align__(16) float smF[];
    uint32_t sbase;
    asm("{ .reg .u64 t; cvta.to.shared.u64 t, %1; cvt.u32.u64 %0, t; }"
        : "=r"(sbase) : "l"((const void*)smF));
    int tid = threadIdx.x, warp = tid >> 5, lane = tid & 31;
    int r0 = blockIdx.x * 16;

    for (int idx = tid; idx < 16 * 256; idx += 256) {
        int r = idx >> 8, c = idx & 255;
        sts1u(sbase + astf(r, c), f2tf(g_attnout[(r0 + r) * 256 + c]));
    }
    prefB32(sbase + P_W0, g_wo_t, tid);

    float acc[4][4];
    run_gemm_tf(sbase, g_wo_t, acc, warp, lane, tid);

    float* red = smF + P_RED / 4;
    float* stt = smF + P_STAT / 4;
    int quad = lane >> 2, q = lane & 3;
    float v[4][4];
    float sl = 0.f, sh = 0.f, ql = 0.f, qh = 0.f;
#pragma unroll
    for (int t = 0; t < 4; t++) {
        int cb = warp * 32 + t * 8 + q * 2;
        float2 bias = *(const float2*)(bo + cb);
        float2 rlo = *(const float2*)(x + (r0 + quad) * 256 + cb);
        float2 rhi = *(const float2*)(x + (r0 + quad + 8) * 256 + cb);
        float v00 = acc[t][0] + bias.x + rlo.x, v01 = acc[t][1] + bias.y + rlo.y;
        float v10 = acc[t][2] + bias.x + rhi.x, v11 = acc[t][3] + bias.y + rhi.y;
        v[t][0] = v00; v[t][1] = v01; v[t][2] = v10; v[t][3] = v11;
        sl += v00 + v01; ql += v00 * v00 + v01 * v01;
        sh += v10 + v11; qh += v10 * v10 + v11 * v11;
    }
#pragma unroll
    for (int o = 1; o < 4; o <<= 1) {
        sl += __shfl_xor_sync(0xffffffffu, sl, o);
        sh += __shfl_xor_sync(0xffffffffu, sh, o);
        ql += __shfl_xor_sync(0xffffffffu, ql, o);
        qh += __shfl_xor_sync(0xffffffffu, qh, o);
    }
    if (q == 0) {
        red[warp * 16 + quad] = sl;
        red[warp * 16 + quad + 8] = sh;
        red[128 + warp * 16 + quad] = ql;
        red[128 + warp * 16 + quad + 8] = qh;
    }
    __syncthreads();
    if (tid < 16) {
        float ts = 0.f, tq = 0.f;
#pragma unroll
        for (int w = 0; w < 8; w++) { ts += red[w * 16 + tid]; tq += red[128 + w * 16 + tid]; }
        float mean = ts * (1.f / 256.f);
        float rstd = rsqrtf(tq * (1.f / 256.f) - mean * mean + EPSLN);
        stt[tid] = rstd; stt[16 + tid] = -mean * rstd;
    }
    __syncthreads();
    float Al = stt[quad], Bl = stt[16 + quad];
    float Ah = stt[quad + 8], Bh = stt[16 + quad + 8];
#pragma unroll
    for (int t = 0; t < 4; t++) {
        int cb = warp * 32 + t * 8 + q * 2;
        float2 gg = *(const float2*)(g1 + cb);
        float2 nn = *(const float2*)(b1 + cb);
        float2 olo, ohi;
        olo.x = (v[t][0] * Al + Bl) * gg.x + nn.x;
        olo.y = (v[t][1] * Al + Bl) * gg.y + nn.y;
        ohi.x = (v[t][2] * Ah + Bh) * gg.x + nn.x;
        ohi.y = (v[t][3] * Ah + Bh) * gg.y + nn.y;
        *(float2*)(g_x1 + (r0 + quad) * 256 + cb) = olo;
        *(float2*)(g_x1 + (r0 + quad + 8) * 256 + cb) = ohi;
    }
}

// ---------------------------------------------------------------------------
// ODE kernel: 64 CTAs x 256 threads, 32 rows/CTA (two m16 tiles).
// W1 resident; W2 3-buffer ring; all RK4 state in global fp32.
// ---------------------------------------------------------------------------
__device__ __forceinline__ void prefB(uint32_t sdst, const uint32_t* gsrc, int tid) {
#pragma unroll
    for (int i = 0; i < 4; i++) {
        int off = (tid + i * 256) * 16;
        cp_async16(sdst + off, (const char*)gsrc + off);
    }
    cp_commit();
}

__device__ __forceinline__ void run_gemm1(uint32_t sbase, float acc[2][4][4], int warp, int lane) {
    int quad = lane >> 2, q = lane & 3;
#pragma unroll
    for (int tl = 0; tl < 2; tl++)
#pragma unroll
        for (int t = 0; t < 4; t++)
#pragma unroll
            for (int j = 0; j < 4; j++) acc[tl][t][j] = 0.f;
    uint32_t aBase = sbase + OFF_AST + (uint32_t)(quad * 32 + q * 8);
    uint32_t bBase = (uint32_t)(warp * 1024 + quad * 32 + q * 8);
#pragma unroll 2
    for (int p = 0; p < 8; p++) {
        uint32_t wb = sbase + OFF_W1R + p * 16384 + bBase;
#pragma unroll
        for (int cc = 0; cc < 2; cc++) {
            int c = p * 2 + cc;
            uint32_t a00, a01, a02, a03, a10, a11, a12, a13;
            lds2u(aBase + c * 1024, a00, a02);
            lds2u(aBase + c * 1024 + 256, a01, a03);
            lds2u(aBase + c * 1024 + 512, a10, a12);
            lds2u(aBase + c * 1024 + 768, a11, a13);
            uint32_t bb = wb + cc * 8192;
#pragma unroll
            for (int t = 0; t < 4; t++) {
                uint32_t b0, b1;
                lds2u(bb + t * 256, b0, b1);
                mma_bf(acc[0][t][0], acc[0][t][1], acc[0][t][2], acc[0][t][3],
                       a00, a01, a02, a03, b0, b1);
                mma_bf(acc[1][t][0], acc[1][t][1], acc[1][t][2], acc[1][t][3],
                       a10, a11, a12, a13, b0, b1);
            }
        }
    }
}

__device__ __forceinline__ void run_gemm2(uint32_t sbase, float acc[2][4][4],
                                          int warp, int lane, int tid) {
    int quad = lane >> 2, q = lane & 3;
#pragma unroll
    for (int tl = 0; tl < 2; tl++)
#pragma unroll
        for (int t = 0; t < 4; t++)
#pragma unroll
            for (int j = 0; j < 4; j++) acc[tl][t][j] = 0.f;
    uint32_t aBase = sbase + OFF_AST + (uint32_t)(quad * 32 + q * 8);
    uint32_t bBase = (uint32_t)(warp * 1024 + quad * 32 + q * 8);
    const uint32_t W2B[3] = { OFF_W20, OFF_W21, OFF_W22 };
    for (int p = 0; p < 8; p++) {
        if (p < 7) cp_wait1(); else cp_wait0();
        __syncthreads();
        if (p < 6) prefB(sbase + W2B[(p + 2) % 3], g_wt2 + (p + 2) * 4096, tid);
        uint32_t wb = sbase + W2B[p % 3] + bBase;
#pragma unroll
        for (int cc = 0; cc < 2; cc++) {
            int c = p * 2 + cc;
            uint32_t a00, a01, a02, a03, a10, a11, a12, a13;
            lds2u(aBase + c * 1024, a00, a02);
            lds2u(aBase + c * 1024 + 256, a01, a03);
            lds2u(aBase + c * 1024 + 512, a10, a12);
            lds2u(aBase + c * 1024 + 768, a11, a13);
            uint32_t bb = wb + cc * 8192;
#pragma unroll
            for (int t = 0; t < 4; t++) {
                uint32_t b0, b1;
                lds2u(bb + t * 256, b0, b1);
                mma_bf(acc[0][t][0], acc[0][t][1], acc[0][t][2], acc[0][t][3],
                       a00, a01, a02, a03, b0, b1);
                mma_bf(acc[1][t][0], acc[1][t][1], acc[1][t][2], acc[1][t][3],
                       a10, a11, a12, a13, b0, b1);
            }
        }
    }
}

template <int ST>
__device__ __forceinline__ void epi2(float* smF, uint32_t sbase, float acc[2][4][4],
                                     int warp, int lane, int tid, int r0) {
    int quad = lane >> 2, q = lane & 3;
    const float* RES = (ST == 0) ? g_ys : g_arg;
    float* CST = smF + OFF_CST / 4;
    float* red = smF + OFF_RED / 4;
    float* stt = smF + OFF_STAT / 4;
    float sum[4] = {0.f, 0.f, 0.f, 0.f}, sq[4] = {0.f, 0.f, 0.f, 0.f};
#pragma unroll
    for (int tl = 0; tl < 2; tl++) {
#pragma unroll
        for (int t = 0; t < 4; t++) {
            int cb = warp * 32 + t * 8 + q * 2;
            float2 bias = *(float2*)(CST + 256 + cb);
            int gl = (r0 + tl * 16 + quad) * 256 + cb;
            float2 rlo = *(const float2*)(RES + gl);
            float2 rhi = *(const float2*)(RES + gl + 2048);
            float v00 = acc[tl][t][0] + bias.x + rlo.x;
            float v01 = acc[tl][t][1] + bias.y + rlo.y;
            float v10 = acc[tl][t][2] + bias.x + rhi.x;
            float v11 = acc[tl][t][3] + bias.y + rhi.y;
            acc[tl][t][0] = v00; acc[tl][t][1] = v01;
            acc[tl][t][2] = v10; acc[tl][t][3] = v11;
            sum[tl * 2] += v00 + v01;     sq[tl * 2] += v00 * v00 + v01 * v01;
            sum[tl * 2 + 1] += v10 + v11; sq[tl * 2 + 1] += v10 * v10 + v11 * v11;
        }
    }
#pragma unroll
    for (int o = 1; o < 4; o <<= 1) {
#pragma unroll
        for (int i = 0; i < 4; i++) {
            sum[i] += __shfl_xor_sync(0xffffffffu, sum[i], o);
            sq[i]  += __shfl_xor_sync(0xffffffffu, sq[i], o);
        }
    }
    if (q == 0) {
#pragma unroll
        for (int i = 0; i < 4; i++) {
            int rloc = (i >> 1) * 16 + (i & 1) * 8 + quad;
            red[warp * 32 + rloc] = sum[i];
            red[256 + warp * 32 + rloc] = sq[i];
        }
    }
    __syncthreads();
    if (tid < 32) {
        float ts = 0.f, tq = 0.f;
#pragma unroll
        for (int w = 0; w < 8; w++) { ts += red[w * 32 + tid]; tq += red[256 + w * 32 + tid]; }
        float mean = ts * (1.f / 256.f);
        float rstd = rsqrtf(tq * (1.f / 256.f) - mean * mean + EPSLN);
        stt[tid] = rstd; stt[32 + tid] = -mean * rstd;
    }
    __syncthreads();
#pragma unroll
    for (int tl = 0; tl < 2; tl++) {
        float Al = stt[tl * 16 + quad], Bl = stt[32 + tl * 16 + quad];
        float Ah = stt[tl * 16 + 8 + quad], Bh = stt[32 + tl * 16 + 8 + quad];
#pragma unroll
        for (int t = 0; t < 4; t++) {
            int cb = warp * 32 + t * 8 + q * 2;
            int gl = (r0 + tl * 16 + quad) * 256 + cb;
            int gh = gl + 2048;
            float2 gg = *(float2*)(CST + 512 + cb);
            float2 nn = *(float2*)(CST + 768 + cb);
            float k00 = (acc[tl][t][0] * Al + Bl) * gg.x + nn.x;
            float k01 = (acc[tl][t][1] * Al + Bl) * gg.y + nn.y;
            float k10 = (acc[tl][t][2] * Ah + Bh) * gg.x + nn.x;
            float k11 = (acc[tl][t][3] * Ah + Bh) * gg.y + nn.y;
            float2 ylo = *(const float2*)(g_ys + gl), yhi = *(const float2*)(g_ys + gh);
            float a00, a01, a10, a11;
            if (ST == 0) {
                *(float2*)(g_k1 + gl) = make_float2(k00, k01);
                *(float2*)(g_k1 + gh) = make_float2(k10, k11);
                const float c3 = DT * (1.f / 3.f);
                a00 = ylo.x + c3 * k00; a01 = ylo.y + c3 * k01;
                a10 = yhi.x + c3 * k10; a11 = yhi.y + c3 * k11;
            } else if (ST == 1) {
                float2 k1l = *(const float2*)(g_k1 + gl), k1h = *(const float2*)(g_k1 + gh);
                *(float2*)(g_k2 + gl) = make_float2(k00, k01);
                *(float2*)(g_k2 + gh) = make_float2(k10, k11);
                a00 = ylo.x + DT * (k00 - (1.f / 3.f) * k1l.x);
                a01 = ylo.y + DT * (k01 - (1.f / 3.f) * k1l.y);
                a10 = yhi.x + DT * (k10 - (1.f / 3.f) * k1h.x);
                a11 = yhi.y + DT * (k11 - (1.f / 3.f) * k1h.y);
            } else if (ST == 2) {
                float2 k1l = *(const float2*)(g_k1 + gl), k1h = *(const float2*)(g_k1 + gh);
                float2 k2l = *(const float2*)(g_k2 + gl), k2h = *(const float2*)(g_k2 + gh);
                *(float2*)(g_k3 + gl) = make_float2(k00, k01);
                *(float2*)(g_k3 + gh) = make_float2(k10, k11);
                a00 = ylo.x + DT * (k1l.x - k2l.x + k00);
                a01 = ylo.y + DT * (k1l.y - k2l.y + k01);
                a10 = yhi.x + DT * (k1h.x - k2h.x + k10);
                a11 = yhi.y + DT * (k1h.y - k2h.y + k11);
            } else {
                float2 k1l = *(const float2*)(g_k1 + gl), k1h = *(const float2*)(g_k1 + gh);
                float2 k2l = *(const float2*)(g_k2 + gl), k2h = *(const float2*)(g_k2 + gh);
                float2 k3l = *(const float2*)(g_k3 + gl), k3h = *(const float2*)(g_k3 + gh);
                a00 = ylo.x + (DT * 0.125f) * (k1l.x + 3.f * (k2l.x + k3l.x) + k00);
                a01 = ylo.y + (DT * 0.125f) * (k1l.y + 3.f * (k2l.y + k3l.y) + k01);
                a10 = yhi.x + (DT * 0.125f) * (k1h.x + 3.f * (k2h.x + k3h.x) + k10);
                a11 = yhi.y + (DT * 0.125f) * (k1h.y + 3.f * (k2h.y + k3h.y) + k11);
            }
            if (ST < 3) {
                *(float2*)(g_arg + gl) = make_float2(a00, a01);
                *(float2*)(g_arg + gh) = make_float2(a10, a11);
            } else {
                *(float2*)(g_ys + gl) = make_float2(a00, a01);
                *(float2*)(g_ys + gh) = make_float2(a10, a11);
            }
            sts1u(sbase + astb3(tl * 16 + quad, cb), f2bf2(a00, a01));
            sts1u(sbase + astb3(tl * 16 + 8 + quad, cb), f2bf2(a10, a11));
        }
    }
}

__global__ void __launch_bounds__(256, 1)
ode_mma_kernel(const int* __restrict__ lead, const int* __restrict__ nsp,
               const float* __restrict__ bl1, const float* __restrict__ bl2,
               const float* __restrict__ gn, const float* __restrict__ bn) {
    extern __shared__ __align__(16) float smF[];
    uint32_t sbase;
    asm("{ .reg .u64 t; cvta.to.shared.u64 t, %1; cvt.u32.u64 %0, t; }"
        : "=r"(sbase) : "l"((const void*)smF));
    int tid = threadIdx.x, warp = tid >> 5, lane = tid & 31;
    int r0 = blockIdx.x * 32;
    int steps = lead[r0 >> 8];
    int ns = nsp ? nsp[0] : 50;
    if (steps > ns) steps = ns;
    if (steps < 0) steps = 0;

    // load W1 resident (one cp.async group)
#pragma unroll
    for (int i = 0; i < 32; i++) {
        int off = (tid + i * 256) * 16;
        cp_async16(sbase + OFF_W1R + off, (const char*)g_wt1 + off);
    }
    cp_commit();

    float* CST = smF + OFF_CST / 4;
    for (int i = tid; i < 256; i += 256) {
        CST[i] = bl1[i]; CST[256 + i] = bl2[i];
        CST[512 + i] = gn[i]; CST[768 + i] = bn[i];
    }
    // x1 -> g_ys + A-stage
    for (int idx = tid; idx < 32 * 128; idx += 256) {
        int r = idx >> 7, kp = idx & 127;
        int cb = kp * 2;
        float2 vv = *(const float2*)(g_x1 + (r0 + r) * 256 + cb);
        *(float2*)(g_ys + (r0 + r) * 256 + cb) = vv;
        sts1u(sbase + astb3(r, cb), f2bf2(vv.x, vv.y));
    }
    cp_wait0();
    __syncthreads();

    float acc[2][4][4];
    for (int s = 0; s < steps; s++) {
#pragma unroll 1
        for (int st = 0; st < 4; st++) {
            // prime W2 blocks 0,1 (overlaps GEMM1)
            prefB(sbase + OFF_W20, g_wt2, tid);
            prefB(sbase + OFF_W21, g_wt2 + 4096, tid);
            run_gemm1(sbase, acc, warp, lane);
            __syncthreads();
            // epi1: h1 = relu(acc + bl1) -> A-stage (bf16)
            {
                int quad = lane >> 2, q = lane & 3;
#pragma unroll
                for (int tl = 0; tl < 2; tl++)
#pragma unroll
                    for (int t = 0; t < 4; t++) {
                        int cb = warp * 32 + t * 8 + q * 2;
                        float2 bias = *(float2*)(CST + cb);
                        sts1u(sbase + astb3(tl * 16 + quad, cb),
                              f2bf2(fmaxf(acc[tl][t][0] + bias.x, 0.f),
                                    fmaxf(acc[tl][t][1] + bias.y, 0.f)));
                        sts1u(sbase + astb3(tl * 16 + 8 + quad, cb),
                              f2bf2(fmaxf(acc[tl][t][2] + bias.x, 0.f),
                                    fmaxf(acc[tl][t][3] + bias.y, 0.f)));
                    }
            }
            // GEMM2's first wait+sync publishes epi1 stores
            run_gemm2(sbase, acc, warp, lane, tid);
            if (st == 0)      epi2<0>(smF, sbase, acc, warp, lane, tid, r0);
            else if (st == 1) epi2<1>(smF, sbase, acc, warp, lane, tid, r0);
            else if (st == 2) epi2<2>(smF, sbase, acc, warp, lane, tid, r0);
            else              epi2<3>(smF, sbase, acc, warp, lane, tid, r0);
            __syncthreads();
        }
    }
}

// ---------------------------------------------------------------------------
// K5: out = LN(x1 + ys; g2,b2)
// ---------------------------------------------------------------------------
__global__ void final_ln_kernel(const float* __restrict__ g2, const float* __restrict__ b2,
                                float* __restrict__ out) {
    int tid = threadIdx.x, lane = tid & 31, w = tid >> 5;
    int r = blockIdx.x * 8 + w;
    float v[8], ls = 0.f, lq = 0.f;
#pragma unroll
    for (int u = 0; u < 8; u++) {
        int c = lane + 32 * u;
        float t = g_x1[r * CDIM + c] + g_ys[r * CDIM + c];
        v[u] = t; ls += t; lq += t * t;
    }
#pragma unroll
    for (int o = 16; o > 0; o >>= 1) {
        ls += __shfl_xor_sync(0xffffffffu, ls, o);
        lq += __shfl_xor_sync(0xffffffffu, lq, o);
    }
    float mean = ls * (1.f / 256.f);
    float rstd = rsqrtf(lq * (1.f / 256.f) - mean * mean + EPSLN);
#pragma unroll
    for (int u = 0; u < 8; u++) {
        int c = lane + 32 * u;
        out[r * CDIM + c] = (v[u] - mean) * rstd * g2[c] + b2[c];
    }
}

// ---------------------------------------------------------------------------
// Launch
// ---------------------------------------------------------------------------
extern "C" void kernel_launch(void* const* d_in, const int* in_sizes, int n_in,
                              void* d_out, int out_size) {
    const float* x    = (const float*)d_in[0];
    const float* wqkv = (const float*)d_in[1];
    const float* bqkv = (const float*)d_in[2];
    const float* wo   = (const float*)d_in[3];
    const float* bo   = (const float*)d_in[4];
    const float* g1   = (const float*)d_in[5];
    const float* b1   = (const float*)d_in[6];
    const float* g2   = (const float*)d_in[7];
    const float* b2   = (const float*)d_in[8];
    const float* wl1  = (const float*)d_in[9];
    const float* bl1  = (const float*)d_in[10];
    const float* wl2  = (const float*)d_in[11];
    const float* bl2  = (const float*)d_in[12];
    const float* gn   = (const float*)d_in[13];
    const float* bn   = (const float*)d_in[14];
    const int* lead   = (const int*)d_in[15];
    const int* nsteps = (n_in > 16) ? (const int*)d_in[16] : nullptr;
    float* out = (float*)d_out;

    cudaFuncSetAttribute(attn_kernel, cudaFuncAttributeMaxDynamicSharedMemorySize, ATTN_SMEM);
    cudaFuncSetAttribute(ode_mma_kernel, cudaFuncAttributeMaxDynamicSharedMemorySize, ODE_SMEM);
    cudaFuncSetAttribute(qkv_mma_kernel, cudaFuncAttributeMaxDynamicSharedMemorySize, QKV_SMEM);
    cudaFuncSetAttribute(proj_mma_kernel, cudaFuncAttributeMaxDynamicSharedMemorySize, PROJ_SMEM);

    prep_w_kernel<<<128, 256>>>(wl1, wl2);
    prep_qkv_kernel<<<dim3(256, 3), 256>>>(wqkv);
    prep_wo_kernel<<<256, 256>>>(wo);
    qkv_mma_kernel<<<dim3(128, 3), 256, QKV_SMEM>>>(x, bqkv);
    attn_kernel<<<128, 256, ATTN_SMEM>>>();
    proj_mma_kernel<<<128, 256, PROJ_SMEM>>>(x, bo, g1, b1);
    ode_mma_kernel<<<64, 256, ODE_SMEM>>>(lead, nsteps, bl1, bl2, gn, bn);
    final_ln_kernel<<<256, 256>>>(g2, b2, out);
}

// round 15
// speedup vs baseline: 2.1143x; 2.1143x over previous
#include <cuda_runtime.h>
#include <math.h>
#include <stdint.h>

#define EPSLN 1e-5f
#define DT    0.01f
#define CDIM  256
#define BDIM  8
#define NTOK  256
#define HEADS 8
#define HD    32
#define ROWS  (BDIM * NTOK)

#define RMJ   264   // row-major state stride (floats)

// ---- ODE smem layout (bytes) ----
#define OFF_YS   0          // 16896
#define OFF_AR   16896      // 16896
#define OFF_AST  33792      // 8192 (bf16 A-stage)
#define OFF_W1R  41984      // 131072 (W1 resident, bf16 MMA-B layout)
#define OFF_W20  173056     // 16384
#define OFF_W21  189440     // 16384
#define OFF_W22  205824     // 16384
#define OFF_RED  222208     // 1024
#define OFF_STAT 223232     // 128
#define OFF_CST  223360     // 4096
#define ODE_SMEM 227456

// ---- prologue mma kernels smem layout (bytes) ----
#define P_AST    0          // 16 KB tf32 A-stage
#define P_W0     16384      // 32 KB
#define P_W1     49152      // 32 KB
#define P_RED    81920      // 256 floats
#define P_STAT   82944      // 32 floats
#define QKV_SMEM 81920
#define PROJ_SMEM 83072

// ---------------------------------------------------------------------------
// Scratch globals
// ---------------------------------------------------------------------------
__device__ float g_qbuf[3 * BDIM * HEADS * NTOK * HD];
__device__ float g_attnout[ROWS * CDIM];
__device__ float g_x1[ROWS * CDIM];
__device__ float g_k1[ROWS * CDIM];
__device__ float g_k2[ROWS * CDIM];
__device__ float g_k3[ROWS * CDIM];
// bf16-pair ODE weights in MMA-B layout
__device__ uint32_t g_wt1[CDIM * CDIM / 2];
__device__ uint32_t g_wt2[CDIM * CDIM / 2];
// tf32 MMA-B layout prologue weights
__device__ float g_wqkv_t[CDIM * 768];
__device__ float g_wo_t[CDIM * CDIM];

// ---------------------------------------------------------------------------
// helpers
// ---------------------------------------------------------------------------
__device__ __forceinline__ uint32_t f2bf2(float lo, float hi) {
    uint32_t r; asm("cvt.rn.bf16x2.f32 %0, %1, %2;" : "=r"(r) : "f"(hi), "f"(lo)); return r;
}
__device__ __forceinline__ uint32_t f2tf(float f) {
    uint32_t r; asm("cvt.rna.tf32.f32 %0, %1;" : "=r"(r) : "f"(f)); return r;
}
__device__ __forceinline__ void lds2u(uint32_t a, uint32_t& x, uint32_t& y) {
    asm volatile("ld.shared.v2.b32 {%0,%1}, [%2];" : "=r"(x), "=r"(y) : "r"(a));
}
__device__ __forceinline__ void sts1u(uint32_t a, uint32_t v) {
    asm volatile("st.shared.b32 [%0], %1;" :: "r"(a), "r"(v));
}
__device__ __forceinline__ void cp_async16(uint32_t sdst, const void* gsrc) {
    asm volatile("cp.async.cg.shared.global [%0], [%1], 16;" :: "r"(sdst), "l"(gsrc));
}
__device__ __forceinline__ void cp_commit() { asm volatile("cp.async.commit_group;"); }
__device__ __forceinline__ void cp_wait1() { asm volatile("cp.async.wait_group 1;" ::: "memory"); }
__device__ __forceinline__ void cp_wait0() { asm volatile("cp.async.wait_group 0;" ::: "memory"); }

__device__ __forceinline__ void mma_bf(float& c0, float& c1, float& c2, float& c3,
                                       uint32_t a0, uint32_t a1, uint32_t a2, uint32_t a3,
                                       uint32_t b0, uint32_t b1) {
    asm volatile(
        "mma.sync.aligned.m16n8k16.row.col.f32.bf16.bf16.f32 "
        "{%0,%1,%2,%3},{%4,%5,%6,%7},{%8,%9},{%0,%1,%2,%3};"
        : "+f"(c0), "+f"(c1), "+f"(c2), "+f"(c3)
        : "r"(a0), "r"(a1), "r"(a2), "r"(a3), "r"(b0), "r"(b1));
}
__device__ __forceinline__ void mma_tf(float& c0, float& c1, float& c2, float& c3,
                                       uint32_t a0, uint32_t a1, uint32_t a2, uint32_t a3,
                                       uint32_t b0, uint32_t b1) {
    asm volatile(
        "mma.sync.aligned.m16n8k8.row.col.f32.tf32.tf32.f32 "
        "{%0,%1,%2,%3},{%4,%5,%6,%7},{%8,%9},{%0,%1,%2,%3};"
        : "+f"(c0), "+f"(c1), "+f"(c2), "+f"(c3)
        : "r"(a0), "r"(a1), "r"(a2), "r"(a3), "r"(b0), "r"(b1));
}

// bf16 A-stage byte offset (ODE)
__device__ __forceinline__ uint32_t astb2(int r, int cb) {
    int pc = (cb >> 1) & 7;
    return OFF_AST + (uint32_t)((cb >> 4) * 512 + r * 32 + ((pc & 3) * 2 + (pc >> 2)) * 4);
}
// tf32 A-stage byte offset (prologue)
__device__ __forceinline__ uint32_t astf(int r, int c) {
    return P_AST + (uint32_t)((c >> 3) * 512 + r * 32 + (c & 3) * 8 + ((c >> 2) & 1) * 4);
}

// ---------------------------------------------------------------------------
// prep kernels
// ---------------------------------------------------------------------------
__global__ void prep_w_kernel(const float* __restrict__ wl1, const float* __restrict__ wl2) {
    int idx = blockIdx.x * 256 + threadIdx.x;
    int kp = idx >> 8, n = idx & 255;
    int k = kp * 2;
    int pc = kp & 7;
    int dst = (k >> 5) * 4096 + ((k >> 4) & 1) * 2048 + n * 8 + (pc & 3) * 2 + (pc >> 2);
    g_wt1[dst] = f2bf2(wl1[k * 256 + n], wl1[(k + 1) * 256 + n]);
    g_wt2[dst] = f2bf2(wl2[k * 256 + n], wl2[(k + 1) * 256 + n]);
}
__global__ void prep_qkv_kernel(const float* __restrict__ wqkv) {
    int k = blockIdx.x, n = threadIdx.x, g = blockIdx.y;
    int dst = g * 65536 + (k >> 5) * 8192 + ((k >> 3) & 3) * 2048 + n * 8 + (k & 3) * 2 + ((k >> 2) & 1);
    g_wqkv_t[dst] = __uint_as_float(f2tf(wqkv[k * 768 + g * 256 + n]));
}
__global__ void prep_wo_kernel(const float* __restrict__ wo) {
    int k = blockIdx.x, n = threadIdx.x;
    int dst = (k >> 5) * 8192 + ((k >> 3) & 3) * 2048 + n * 8 + (k & 3) * 2 + ((k >> 2) & 1);
    g_wo_t[dst] = __uint_as_float(f2tf(wo[k * 256 + n]));
}

// ---------------------------------------------------------------------------
// prologue tf32 GEMM core
// ---------------------------------------------------------------------------
__device__ __forceinline__ void prefB32(uint32_t sdst, const float* gsrc, int tid) {
#pragma unroll
    for (int i = 0; i < 8; i++) {
        int off = (tid + i * 256) * 16;
        cp_async16(sdst + off, (const char*)gsrc + off);
    }
    cp_commit();
}

__device__ __forceinline__ void run_gemm_tf(uint32_t sbase, const float* gw,
                                            float acc[4][4], int warp, int lane, int tid) {
    int quad = lane >> 2, q = lane & 3;
#pragma unroll
    for (int t = 0; t < 4; t++)
#pragma unroll
        for (int j = 0; j < 4; j++) acc[t][j] = 0.f;
    uint32_t aBase = sbase + P_AST + (uint32_t)(quad * 32 + q * 8);
    uint32_t bBase = (uint32_t)(warp * 1024 + quad * 32 + q * 8);
    for (int p = 0; p < 8; p++) {
        if (p < 7) {
            prefB32(sbase + (((p + 1) & 1) ? P_W1 : P_W0), gw + (p + 1) * 8192, tid);
            cp_wait1();
        } else {
            cp_wait0();
        }
        __syncthreads();
        uint32_t wb = sbase + ((p & 1) ? P_W1 : P_W0) + bBase;
#pragma unroll
        for (int kc4 = 0; kc4 < 4; kc4++) {
            int kcg = p * 4 + kc4;
            uint32_t a0, a1, a2, a3;
            lds2u(aBase + kcg * 512, a0, a2);
            lds2u(aBase + kcg * 512 + 256, a1, a3);
            uint32_t bb = wb + kc4 * 8192;
#pragma unroll
            for (int t = 0; t < 4; t++) {
                uint32_t b0, b1;
                lds2u(bb + t * 256, b0, b1);
                mma_tf(acc[t][0], acc[t][1], acc[t][2], acc[t][3], a0, a1, a2, a3, b0, b1);
            }
        }
    }
}

// ---------------------------------------------------------------------------
// K1: qkv via tf32 mma
// ---------------------------------------------------------------------------
__global__ void __launch_bounds__(256, 1)
qkv_mma_kernel(const float* __restrict__ x, const float* __restrict__ bqkv) {
    extern __shared__ __align__(16) float smF[];
    uint32_t sbase;
    asm("{ .reg .u64 t; cvta.to.shared.u64 t, %1; cvt.u32.u64 %0, t; }"
        : "=r"(sbase) : "l"((const void*)smF));
    int tid = threadIdx.x, warp = tid >> 5, lane = tid & 31;
    int r0 = blockIdx.x * 16, g = blockIdx.y;

    for (int idx = tid; idx < 16 * 256; idx += 256) {
        int r = idx >> 8, c = idx & 255;
        sts1u(sbase + astf(r, c), f2tf(x[(r0 + r) * 256 + c]));
    }
    prefB32(sbase + P_W0, g_wqkv_t + g * 65536, tid);

    float acc[4][4];
    run_gemm_tf(sbase, g_wqkv_t + g * 65536, acc, warp, lane, tid);

    int quad = lane >> 2, q = lane & 3;
#pragma unroll
    for (int t = 0; t < 4; t++) {
        int cb = warp * 32 + t * 8 + q * 2;
        float2 bias = *(const float2*)(bqkv + g * 256 + cb);
        int h = cb >> 5, d = cb & 31;
#pragma unroll
        for (int half = 0; half < 2; half++) {
            int r = r0 + quad + half * 8;
            int b = r >> 8, n = r & 255;
            float2 ov;
            ov.x = acc[t][2 * half + 0] + bias.x;
            ov.y = acc[t][2 * half + 1] + bias.y;
            *(float2*)(g_qbuf + (((g * BDIM + b) * HEADS + h) * NTOK + n) * HD + d) = ov;
        }
    }
}

// ---------------------------------------------------------------------------
// K2: attention — split over query halves (128 CTAs)
// ---------------------------------------------------------------------------
#define ATTN_SMEM ((3 * 256 * 33 + 8 * 256) * 4)
__global__ void attn_kernel() {
    extern __shared__ float sm[];
    float* qs = sm;
    float* ks = qs + 256 * 33;
    float* vs = ks + 256 * 33;
    float* prob = vs + 256 * 33;
    int tid = threadIdx.x, lane = tid & 31, w = tid >> 5;
    int bh = blockIdx.x >> 1, half = blockIdx.x & 1;
    int b = bh >> 3, h = bh & 7;
    const float scale = 0.17677669529663687f;
    const float* qg = g_qbuf + ((0 * BDIM + b) * HEADS + h) * NTOK * HD;
    const float* kg = g_qbuf + ((1 * BDIM + b) * HEADS + h) * NTOK * HD;
    const float* vg = g_qbuf + ((2 * BDIM + b) * HEADS + h) * NTOK * HD;
    for (int idx = tid; idx < NTOK * HD; idx += 256) {
        int n = idx >> 5, d = idx & 31;
        qs[n * 33 + d] = qg[idx] * scale;
        ks[n * 33 + d] = kg[idx];
        vs[n * 33 + d] = vg[idx];
    }
    __syncthreads();
    for (int n = 128 * half + w; n < 128 * (half + 1); n += 8) {
        float s[8];
#pragma unroll
        for (int u = 0; u < 8; u++) {
            int j = lane + 32 * u;
            float a = 0.f;
#pragma unroll 8
            for (int d = 0; d < HD; d++) a = fmaf(qs[n * 33 + d], ks[j * 33 + d], a);
            s[u] = a;
        }
        float mx = s[0];
#pragma unroll
        for (int u = 1; u < 8; u++) mx = fmaxf(mx, s[u]);
#pragma unroll
        for (int o = 16; o > 0; o >>= 1) mx = fmaxf(mx, __shfl_xor_sync(0xffffffffu, mx, o));
        float sum = 0.f;
#pragma unroll
        for (int u = 0; u < 8; u++) { s[u] = __expf(s[u] - mx); sum += s[u]; }
#pragma unroll
        for (int o = 16; o > 0; o >>= 1) sum += __shfl_xor_sync(0xffffffffu, sum, o);
        float inv = 1.f / sum;
#pragma unroll
        for (int u = 0; u < 8; u++) prob[w * 256 + lane + 32 * u] = s[u] * inv;
        __syncwarp();
        float acc = 0.f;
#pragma unroll 8
        for (int j = 0; j < NTOK; j++) acc = fmaf(prob[w * 256 + j], vs[j * 33 + lane], acc);
        g_attnout[(b * NTOK + n) * CDIM + h * HD + lane] = acc;
        __syncwarp();
    }
}

// ---------------------------------------------------------------------------
// K3: x1 = LN(x + attnout @ wo + bo) via tf32 mma
// ---------------------------------------------------------------------------
__global__ void __launch_bounds__(256, 1)
proj_mma_kernel(const float* __restrict__ x, const float* __restrict__ bo,
                const float* __restrict__ g1, const float* __restrict__ b1) {
    extern __shared__ __align__(16) float smF[];
    uint32_t sbase;
    asm("{ .reg .u64 t; cvta.to.shared.u64 t, %1; cvt.u32.u64 %0, t; }"
        : "=r"(sbase) : "l"((const void*)smF));
    int tid = threadIdx.x, warp = tid >> 5, lane = tid & 31;
    int r0 = blockIdx.x * 16;

    for (int idx = tid; idx < 16 * 256; idx += 256) {
        int r = idx >> 8, c = idx & 255;
        sts1u(sbase + astf(r, c), f2tf(g_attnout[(r0 + r) * 256 + c]));
    }
    prefB32(sbase + P_W0, g_wo_t, tid);

    float acc[4][4];
    run_gemm_tf(sbase, g_wo_t, acc, warp, lane, tid);

    float* red = smF + P_RED / 4;
    float* stt = smF + P_STAT / 4;
    int quad = lane >> 2, q = lane & 3;
    float v[4][4];
    float sl = 0.f, sh = 0.f, ql = 0.f, qh = 0.f;
#pragma unroll
    for (int t = 0; t < 4; t++) {
        int cb = warp * 32 + t * 8 + q * 2;
        float2 bias = *(const float2*)(bo + cb);
        float2 rlo = *(const float2*)(x + (r0 + quad) * 256 + cb);
        float2 rhi = *(const float2*)(x + (r0 + quad + 8) * 256 + cb);
        float v00 = acc[t][0] + bias.x + rlo.x, v01 = acc[t][1] + bias.y + rlo.y;
        float v10 = acc[t][2] + bias.x + rhi.x, v11 = acc[t][3] + bias.y + rhi.y;
        v[t][0] = v00; v[t][1] = v01; v[t][2] = v10; v[t][3] = v11;
        sl += v00 + v01; ql += v00 * v00 + v01 * v01;
        sh += v10 + v11; qh += v10 * v10 + v11 * v11;
    }
#pragma unroll
    for (int o = 1; o < 4; o <<= 1) {
        sl += __shfl_xor_sync(0xffffffffu, sl, o);
        sh += __shfl_xor_sync(0xffffffffu, sh, o);
        ql += __shfl_xor_sync(0xffffffffu, ql, o);
        qh += __shfl_xor_sync(0xffffffffu, qh, o);
    }
    if (q == 0) {
        red[warp * 16 + quad] = sl;
        red[warp * 16 + quad + 8] = sh;
        red[128 + warp * 16 + quad] = ql;
        red[128 + warp * 16 + quad + 8] = qh;
    }
    __syncthreads();
    if (tid < 16) {
        float ts = 0.f, tq = 0.f;
#pragma unroll
        for (int w = 0; w < 8; w++) { ts += red[w * 16 + tid]; tq += red[128 + w * 16 + tid]; }
        float mean = ts * (1.f / 256.f);
        float rstd = rsqrtf(tq * (1.f / 256.f) - mean * mean + EPSLN);
        stt[tid] = rstd; stt[16 + tid] = -mean * rstd;
    }
    __syncthreads();
    float Al = stt[quad], Bl = stt[16 + quad];
    float Ah = stt[quad + 8], Bh = stt[16 + quad + 8];
#pragma unroll
    for (int t = 0; t < 4; t++) {
        int cb = warp * 32 + t * 8 + q * 2;
        float2 gg = *(const float2*)(g1 + cb);
        float2 nn = *(const float2*)(b1 + cb);
        float2 olo, ohi;
        olo.x = (v[t][0] * Al + Bl) * gg.x + nn.x;
        olo.y = (v[t][1] * Al + Bl) * gg.y + nn.y;
        ohi.x = (v[t][2] * Ah + Bh) * gg.x + nn.x;
        ohi.y = (v[t][3] * Ah + Bh) * gg.y + nn.y;
        *(float2*)(g_x1 + (r0 + quad) * 256 + cb) = olo;
        *(float2*)(g_x1 + (r0 + quad + 8) * 256 + cb) = ohi;
    }
}

// ---------------------------------------------------------------------------
// ODE kernel: W1 resident in smem; W2 streamed via 3-buffer ring; k1-3 global.
// Fused output LN at the tail (writes `out` directly).
// ---------------------------------------------------------------------------
__device__ __forceinline__ void prefB(uint32_t sdst, const uint32_t* gsrc, int tid) {
#pragma unroll
    for (int i = 0; i < 4; i++) {
        int off = (tid + i * 256) * 16;
        cp_async16(sdst + off, (const char*)gsrc + off);
    }
    cp_commit();
}

// GEMM1: W1 resident — no waits, no barriers
__device__ __forceinline__ void run_gemm1(uint32_t sbase, float acc[4][4], int warp, int lane) {
    int quad = lane >> 2, q = lane & 3;
#pragma unroll
    for (int t = 0; t < 4; t++)
#pragma unroll
        for (int j = 0; j < 4; j++) acc[t][j] = 0.f;
    uint32_t aBase = sbase + OFF_AST + (uint32_t)(quad * 32 + q * 8);
    uint32_t bBase = (uint32_t)((warp * 32 + quad) * 32 + q * 8);
#pragma unroll 2
    for (int p = 0; p < 8; p++) {
        uint32_t wb = sbase + OFF_W1R + p * 16384 + bBase;
#pragma unroll
        for (int cc = 0; cc < 2; cc++) {
            int c = p * 2 + cc;
            uint32_t a0, a1, a2, a3;
            lds2u(aBase + c * 512, a0, a2);
            lds2u(aBase + c * 512 + 256, a1, a3);
            uint32_t bb = wb + cc * 8192;
#pragma unroll
            for (int t = 0; t < 4; t++) {
                uint32_t b0, b1;
                lds2u(bb + t * 256, b0, b1);
                mma_bf(acc[t][0], acc[t][1], acc[t][2], acc[t][3], a0, a1, a2, a3, b0, b1);
            }
        }
    }
}

// GEMM2: W2 streamed, 3-buffer ring (prefetch after barrier: race-free)
__device__ __forceinline__ void run_gemm2(uint32_t sbase, float acc[4][4],
                                          int warp, int lane, int tid) {
    int quad = lane >> 2, q = lane & 3;
#pragma unroll
    for (int t = 0; t < 4; t++)
#pragma unroll
        for (int j = 0; j < 4; j++) acc[t][j] = 0.f;
    uint32_t aBase = sbase + OFF_AST + (uint32_t)(quad * 32 + q * 8);
    uint32_t bBase = (uint32_t)((warp * 32 + quad) * 32 + q * 8);
    const uint32_t W2B[3] = { OFF_W20, OFF_W21, OFF_W22 };
    for (int p = 0; p < 8; p++) {
        if (p < 7) cp_wait1(); else cp_wait0();
        __syncthreads();
        if (p < 6) prefB(sbase + W2B[(p + 2) % 3], g_wt2 + (p + 2) * 4096, tid);
        uint32_t wb = sbase + W2B[p % 3] + bBase;
#pragma unroll
        for (int cc = 0; cc < 2; cc++) {
            int c = p * 2 + cc;
            uint32_t a0, a1, a2, a3;
            lds2u(aBase + c * 512, a0, a2);
            lds2u(aBase + c * 512 + 256, a1, a3);
            uint32_t bb = wb + cc * 8192;
#pragma unroll
            for (int t = 0; t < 4; t++) {
                uint32_t b0, b1;
                lds2u(bb + t * 256, b0, b1);
                mma_bf(acc[t][0], acc[t][1], acc[t][2], acc[t][3], a0, a1, a2, a3, b0, b1);
            }
        }
    }
}

template <int ST>
__device__ __forceinline__ void epi2(float* smF, uint32_t sbase, float acc[4][4],
                                     int warp, int lane, int tid, int r0) {
    int quad = lane >> 2, q = lane & 3;
    float* RES = smF + ((ST == 0) ? OFF_YS : OFF_AR) / 4;
    float* CST = smF + OFF_CST / 4;
    float* red = smF + OFF_RED / 4;
    float* stt = smF + OFF_STAT / 4;
    float v[4][4];
    float sl = 0.f, sh = 0.f, ql = 0.f, qh = 0.f;
#pragma unroll
    for (int t = 0; t < 4; t++) {
        int cb = warp * 32 + t * 8 + q * 2;
        float2 bias = *(float2*)(CST + 256 + cb);
        float2 rlo = *(float2*)(RES + quad * RMJ + cb);
        float2 rhi = *(float2*)(RES + (quad + 8) * RMJ + cb);
        float v00 = acc[t][0] + bias.x + rlo.x, v01 = acc[t][1] + bias.y + rlo.y;
        float v10 = acc[t][2] + bias.x + rhi.x, v11 = acc[t][3] + bias.y + rhi.y;
        v[t][0] = v00; v[t][1] = v01; v[t][2] = v10; v[t][3] = v11;
        sl += v00 + v01; ql += v00 * v00 + v01 * v01;
        sh += v10 + v11; qh += v10 * v10 + v11 * v11;
    }
#pragma unroll
    for (int o = 1; o < 4; o <<= 1) {
        sl += __shfl_xor_sync(0xffffffffu, sl, o);
        sh += __shfl_xor_sync(0xffffffffu, sh, o);
        ql += __shfl_xor_sync(0xffffffffu, ql, o);
        qh += __shfl_xor_sync(0xffffffffu, qh, o);
    }
    if (q == 0) {
        red[warp * 16 + quad] = sl;
        red[warp * 16 + quad + 8] = sh;
        red[128 + warp * 16 + quad] = ql;
        red[128 + warp * 16 + quad + 8] = qh;
    }
    __syncthreads();
    if (tid < 16) {
        float ts = 0.f, tq = 0.f;
#pragma unroll
        for (int w = 0; w < 8; w++) { ts += red[w * 16 + tid]; tq += red[128 + w * 16 + tid]; }
        float mean = ts * (1.f / 256.f);
        float rstd = rsqrtf(tq * (1.f / 256.f) - mean * mean + EPSLN);
        stt[tid] = rstd; stt[16 + tid] = -mean * rstd;
    }
    __syncthreads();
    float Al = stt[quad], Bl = stt[16 + quad];
    float Ah = stt[quad + 8], Bh = stt[16 + quad + 8];
    float* Y  = smF + OFF_YS / 4;
    float* AR = smF + OFF_AR / 4;
#pragma unroll
    for (int t = 0; t < 4; t++) {
        int cb = warp * 32 + t * 8 + q * 2;
        int ol = quad * RMJ + cb, oh = (quad + 8) * RMJ + cb;
        int gl = (r0 + quad) * 256 + cb, gh = (r0 + quad + 8) * 256 + cb;
        float2 gg = *(float2*)(CST + 512 + cb);
        float2 nn = *(float2*)(CST + 768 + cb);
        float k00 = (v[t][0] * Al + Bl) * gg.x + nn.x;
        float k01 = (v[t][1] * Al + Bl) * gg.y + nn.y;
        float k10 = (v[t][2] * Ah + Bh) * gg.x + nn.x;
        float k11 = (v[t][3] * Ah + Bh) * gg.y + nn.y;
        float2 ylo = *(float2*)(Y + ol), yhi = *(float2*)(Y + oh);
        float a00, a01, a10, a11;
        if (ST == 0) {
            *(float2*)(g_k1 + gl) = make_float2(k00, k01);
            *(float2*)(g_k1 + gh) = make_float2(k10, k11);
            const float c3 = DT * (1.f / 3.f);
            a00 = ylo.x + c3 * k00; a01 = ylo.y + c3 * k01;
            a10 = yhi.x + c3 * k10; a11 = yhi.y + c3 * k11;
        } else if (ST == 1) {
            float2 k1l = *(const float2*)(g_k1 + gl), k1h = *(const float2*)(g_k1 + gh);
            *(float2*)(g_k2 + gl) = make_float2(k00, k01);
            *(float2*)(g_k2 + gh) = make_float2(k10, k11);
            a00 = ylo.x + DT * (k00 - (1.f / 3.f) * k1l.x);
            a01 = ylo.y + DT * (k01 - (1.f / 3.f) * k1l.y);
            a10 = yhi.x + DT * (k10 - (1.f / 3.f) * k1h.x);
            a11 = yhi.y + DT * (k11 - (1.f / 3.f) * k1h.y);
        } else if (ST == 2) {
            float2 k1l = *(const float2*)(g_k1 + gl), k1h = *(const float2*)(g_k1 + gh);
            float2 k2l = *(const float2*)(g_k2 + gl), k2h = *(const float2*)(g_k2 + gh);
            *(float2*)(g_k3 + gl) = make_float2(k00, k01);
            *(float2*)(g_k3 + gh) = make_float2(k10, k11);
            a00 = ylo.x + DT * (k1l.x - k2l.x + k00);
            a01 = ylo.y + DT * (k1l.y - k2l.y + k01);
            a10 = yhi.x + DT * (k1h.x - k2h.x + k10);
            a11 = yhi.y + DT * (k1h.y - k2h.y + k11);
        } else {
            float2 k1l = *(const float2*)(g_k1 + gl), k1h = *(const float2*)(g_k1 + gh);
            float2 k2l = *(const float2*)(g_k2 + gl), k2h = *(const float2*)(g_k2 + gh);
            float2 k3l = *(const float2*)(g_k3 + gl), k3h = *(const float2*)(g_k3 + gh);
            a00 = ylo.x + (DT * 0.125f) * (k1l.x + 3.f * (k2l.x + k3l.x) + k00);
            a01 = ylo.y + (DT * 0.125f) * (k1l.y + 3.f * (k2l.y + k3l.y) + k01);
            a10 = yhi.x + (DT * 0.125f) * (k1h.x + 3.f * (k2h.x + k3h.x) + k10);
            a11 = yhi.y + (DT * 0.125f) * (k1h.y + 3.f * (k2h.y + k3h.y) + k11);
        }
        if (ST < 3) {
            *(float2*)(AR + ol) = make_float2(a00, a01);
            *(float2*)(AR + oh) = make_float2(a10, a11);
        } else {
            *(float2*)(Y + ol) = make_float2(a00, a01);
            *(float2*)(Y + oh) = make_float2(a10, a11);
        }
        sts1u(sbase + astb2(quad, cb), f2bf2(a00, a01));
        sts1u(sbase + astb2(quad + 8, cb), f2bf2(a10, a11));
    }
}

__global__ void __launch_bounds__(256, 1)
ode_mma_kernel(const int* __restrict__ lead, const int* __restrict__ nsp,
               const float* __restrict__ bl1, const float* __restrict__ bl2,
               const float* __restrict__ gn, const float* __restrict__ bn,
               const float* __restrict__ g2, const float* __restrict__ b2,
               float* __restrict__ out) {
    extern __shared__ __align__(16) float smF[];
    uint32_t sbase;
    asm("{ .reg .u64 t; cvta.to.shared.u64 t, %1; cvt.u32.u64 %0, t; }"
        : "=r"(sbase) : "l"((const void*)smF));
    int tid = threadIdx.x, warp = tid >> 5, lane = tid & 31;
    int r0 = blockIdx.x * 16;
    int steps = lead[r0 >> 8];
    int ns = nsp ? nsp[0] : 50;
    if (steps > ns) steps = ns;
    if (steps < 0) steps = 0;

    // load W1 resident (one cp.async group)
#pragma unroll
    for (int i = 0; i < 32; i++) {
        int off = (tid + i * 256) * 16;
        cp_async16(sbase + OFF_W1R + off, (const char*)g_wt1 + off);
    }
    cp_commit();

    float* CST = smF + OFF_CST / 4;
    for (int i = tid; i < 256; i += 256) {
        CST[i] = bl1[i]; CST[256 + i] = bl2[i];
        CST[512 + i] = gn[i]; CST[768 + i] = bn[i];
    }
    for (int idx = tid; idx < 16 * 128; idx += 256) {
        int r = idx >> 7, kp = idx & 127;
        int cb = kp * 2;
        float2 vv = *(const float2*)(g_x1 + (r0 + r) * 256 + cb);
        smF[OFF_YS / 4 + r * RMJ + cb] = vv.x;
        smF[OFF_YS / 4 + r * RMJ + cb + 1] = vv.y;
        sts1u(sbase + astb2(r, cb), f2bf2(vv.x, vv.y));
    }
    cp_wait0();
    __syncthreads();

    float acc[4][4];
    for (int s = 0; s < steps; s++) {
#pragma unroll 1
        for (int st = 0; st < 4; st++) {
            // prime W2 blocks 0,1 (overlaps with GEMM1)
            prefB(sbase + OFF_W20, g_wt2, tid);
            prefB(sbase + OFF_W21, g_wt2 + 4096, tid);
            run_gemm1(sbase, acc, warp, lane);
            __syncthreads();
            // epi1: h1 = relu(acc + bl1) -> A-stage (bf16)
            {
                int quad = lane >> 2, q = lane & 3;
#pragma unroll
                for (int t = 0; t < 4; t++) {
                    int cb = warp * 32 + t * 8 + q * 2;
                    float2 bias = *(float2*)(CST + cb);
                    sts1u(sbase + astb2(quad, cb),
                          f2bf2(fmaxf(acc[t][0] + bias.x, 0.f), fmaxf(acc[t][1] + bias.y, 0.f)));
                    sts1u(sbase + astb2(quad + 8, cb),
                          f2bf2(fmaxf(acc[t][2] + bias.x, 0.f), fmaxf(acc[t][3] + bias.y, 0.f)));
                }
            }
            // GEMM2's internal first wait+sync publishes epi1 stores
            run_gemm2(sbase, acc, warp, lane, tid);
            if (st == 0)      epi2<0>(smF, sbase, acc, warp, lane, tid, r0);
            else if (st == 1) epi2<1>(smF, sbase, acc, warp, lane, tid, r0);
            else if (st == 2) epi2<2>(smF, sbase, acc, warp, lane, tid, r0);
            else              epi2<3>(smF, sbase, acc, warp, lane, tid, r0);
            __syncthreads();
        }
    }
    cp_wait0();
    __syncthreads();

    // ---- fused output LN: out = LN(x1 + ys; g2, b2) ----
#pragma unroll
    for (int rr = 0; rr < 2; rr++) {
        int r = warp * 2 + rr;
        float v[8], ls = 0.f, lq = 0.f;
#pragma unroll
        for (int u = 0; u < 8; u++) {
            int c = lane + 32 * u;
            float t = g_x1[(r0 + r) * 256 + c] + smF[OFF_YS / 4 + r * RMJ + c];
            v[u] = t; ls += t; lq += t * t;
        }
#pragma unroll
        for (int o = 16; o > 0; o >>= 1) {
            ls += __shfl_xor_sync(0xffffffffu, ls, o);
            lq += __shfl_xor_sync(0xffffffffu, lq, o);
        }
        float mean = ls * (1.f / 256.f);
        float rstd = rsqrtf(lq * (1.f / 256.f) - mean * mean + EPSLN);
#pragma unroll
        for (int u = 0; u < 8; u++) {
            int c = lane + 32 * u;
            out[(r0 + r) * 256 + c] = (v[u] - mean) * rstd * g2[c] + b2[c];
        }
    }
}

// ---------------------------------------------------------------------------
// Launch
// ---------------------------------------------------------------------------
extern "C" void kernel_launch(void* const* d_in, const int* in_sizes, int n_in,
                              void* d_out, int out_size) {
    const float* x    = (const float*)d_in[0];
    const float* wqkv = (const float*)d_in[1];
    const float* bqkv = (const float*)d_in[2];
    const float* wo   = (const float*)d_in[3];
    const float* bo   = (const float*)d_in[4];
    const float* g1   = (const float*)d_in[5];
    const float* b1   = (const float*)d_in[6];
    const float* g2   = (const float*)d_in[7];
    const float* b2   = (const float*)d_in[8];
    const float* wl1  = (const float*)d_in[9];
    const float* bl1  = (const float*)d_in[10];
    const float* wl2  = (const float*)d_in[11];
    const float* bl2  = (const float*)d_in[12];
    const float* gn   = (const float*)d_in[13];
    const float* bn   = (const float*)d_in[14];
    const int* lead   = (const int*)d_in[15];
    const int* nsteps = (n_in > 16) ? (const int*)d_in[16] : nullptr;
    float* out = (float*)d_out;

    cudaFuncSetAttribute(attn_kernel, cudaFuncAttributeMaxDynamicSharedMemorySize, ATTN_SMEM);
    cudaFuncSetAttribute(ode_mma_kernel, cudaFuncAttributeMaxDynamicSharedMemorySize, ODE_SMEM);
    cudaFuncSetAttribute(qkv_mma_kernel, cudaFuncAttributeMaxDynamicSharedMemorySize, QKV_SMEM);
    cudaFuncSetAttribute(proj_mma_kernel, cudaFuncAttributeMaxDynamicSharedMemorySize, PROJ_SMEM);

    prep_w_kernel<<<128, 256>>>(wl1, wl2);
    prep_qkv_kernel<<<dim3(256, 3), 256>>>(wqkv);
    prep_wo_kernel<<<256, 256>>>(wo);
    qkv_mma_kernel<<<dim3(128, 3), 256, QKV_SMEM>>>(x, bqkv);
    attn_kernel<<<128, 256, ATTN_SMEM>>>();
    proj_mma_kernel<<<128, 256, PROJ_SMEM>>>(x, bo, g1, b1);
    ode_mma_kernel<<<128, 256, ODE_SMEM>>>(lead, nsteps, bl1, bl2, gn, bn, g2, b2, out);
}

// round 16
// speedup vs baseline: 2.2389x; 1.0589x over previous
#include <cuda_runtime.h>
#include <math.h>
#include <stdint.h>

#define EPSLN 1e-5f
#define DT    0.01f
#define CDIM  256
#define BDIM  8
#define NTOK  256
#define HEADS 8
#define HD    32
#define ROWS  (BDIM * NTOK)

#define RMJ   264   // row-major state stride (floats)

// ---- ODE smem layout (bytes) ----
#define OFF_YS   0          // 16896
#define OFF_AR   16896      // 16896
#define OFF_AST  33792      // 8192 (bf16 A-stage)
#define OFF_W1R  41984      // 131072 (W1 resident, bf16 MMA-B layout)
#define OFF_W20  173056     // 16384
#define OFF_W21  189440     // 16384
#define OFF_W22  205824     // 16384
#define OFF_RED  222208     // 1024
#define OFF_STAT 223232     // 128
#define OFF_CST  223360     // 4096
#define ODE_SMEM 227456

// ---- prologue mma kernels smem layout (bytes) ----
#define P_AST    0          // 16 KB tf32 A-stage
#define P_W0     16384      // 32 KB
#define P_W1     49152      // 32 KB
#define P_RED    81920      // 256 floats
#define P_STAT   82944      // 32 floats
#define QKV_SMEM 81920
#define PROJ_SMEM 83072

// ---------------------------------------------------------------------------
// Scratch globals
// ---------------------------------------------------------------------------
__device__ float g_qbuf[3 * BDIM * HEADS * NTOK * HD];
__device__ float g_attnout[ROWS * CDIM];
__device__ float g_x1[ROWS * CDIM];
__device__ float g_k1[ROWS * CDIM];
__device__ float g_k2[ROWS * CDIM];
__device__ float g_k3[ROWS * CDIM];
// bf16-pair ODE weights in MMA-B layout
__device__ uint32_t g_wt1[CDIM * CDIM / 2];
__device__ uint32_t g_wt2[CDIM * CDIM / 2];
// tf32 MMA-B layout prologue weights
__device__ float g_wqkv_t[CDIM * 768];
__device__ float g_wo_t[CDIM * CDIM];

// ---------------------------------------------------------------------------
// helpers
// ---------------------------------------------------------------------------
__device__ __forceinline__ uint32_t f2bf2(float lo, float hi) {
    uint32_t r; asm("cvt.rn.bf16x2.f32 %0, %1, %2;" : "=r"(r) : "f"(hi), "f"(lo)); return r;
}
__device__ __forceinline__ uint32_t f2tf(float f) {
    uint32_t r; asm("cvt.rna.tf32.f32 %0, %1;" : "=r"(r) : "f"(f)); return r;
}
__device__ __forceinline__ void lds2u(uint32_t a, uint32_t& x, uint32_t& y) {
    asm volatile("ld.shared.v2.b32 {%0,%1}, [%2];" : "=r"(x), "=r"(y) : "r"(a));
}
__device__ __forceinline__ void sts1u(uint32_t a, uint32_t v) {
    asm volatile("st.shared.b32 [%0], %1;" :: "r"(a), "r"(v));
}
__device__ __forceinline__ void cp_async16(uint32_t sdst, const void* gsrc) {
    asm volatile("cp.async.cg.shared.global [%0], [%1], 16;" :: "r"(sdst), "l"(gsrc));
}
__device__ __forceinline__ void cp_commit() { asm volatile("cp.async.commit_group;"); }
__device__ __forceinline__ void cp_wait1() { asm volatile("cp.async.wait_group 1;" ::: "memory"); }
__device__ __forceinline__ void cp_wait0() { asm volatile("cp.async.wait_group 0;" ::: "memory"); }

__device__ __forceinline__ void mma_bf(float& c0, float& c1, float& c2, float& c3,
                                       uint32_t a0, uint32_t a1, uint32_t a2, uint32_t a3,
                                       uint32_t b0, uint32_t b1) {
    asm volatile(
        "mma.sync.aligned.m16n8k16.row.col.f32.bf16.bf16.f32 "
        "{%0,%1,%2,%3},{%4,%5,%6,%7},{%8,%9},{%0,%1,%2,%3};"
        : "+f"(c0), "+f"(c1), "+f"(c2), "+f"(c3)
        : "r"(a0), "r"(a1), "r"(a2), "r"(a3), "r"(b0), "r"(b1));
}
__device__ __forceinline__ void mma_tf(float& c0, float& c1, float& c2, float& c3,
                                       uint32_t a0, uint32_t a1, uint32_t a2, uint32_t a3,
                                       uint32_t b0, uint32_t b1) {
    asm volatile(
        "mma.sync.aligned.m16n8k8.row.col.f32.tf32.tf32.f32 "
        "{%0,%1,%2,%3},{%4,%5,%6,%7},{%8,%9},{%0,%1,%2,%3};"
        : "+f"(c0), "+f"(c1), "+f"(c2), "+f"(c3)
        : "r"(a0), "r"(a1), "r"(a2), "r"(a3), "r"(b0), "r"(b1));
}

// bf16 A-stage byte offset (ODE)
__device__ __forceinline__ uint32_t astb2(int r, int cb) {
    int pc = (cb >> 1) & 7;
    return OFF_AST + (uint32_t)((cb >> 4) * 512 + r * 32 + ((pc & 3) * 2 + (pc >> 2)) * 4);
}
// tf32 A-stage byte offset (prologue)
__device__ __forceinline__ uint32_t astf(int r, int c) {
    return P_AST + (uint32_t)((c >> 3) * 512 + r * 32 + (c & 3) * 8 + ((c >> 2) & 1) * 4);
}

// ---------------------------------------------------------------------------
// fused prep kernel: all weight transforms in one launch. grid 256 x 256 thr.
// ---------------------------------------------------------------------------
__global__ void prep_all_kernel(const float* __restrict__ wl1, const float* __restrict__ wl2,
                                const float* __restrict__ wqkv, const float* __restrict__ wo) {
    int k = blockIdx.x, n = threadIdx.x;
    // wo (tf32 MMA-B)
    {
        int dst = (k >> 5) * 8192 + ((k >> 3) & 3) * 2048 + n * 8 + (k & 3) * 2 + ((k >> 2) & 1);
        g_wo_t[dst] = __uint_as_float(f2tf(wo[k * 256 + n]));
        // wqkv (3 groups)
#pragma unroll
        for (int g = 0; g < 3; g++)
            g_wqkv_t[g * 65536 + dst] = __uint_as_float(f2tf(wqkv[k * 768 + g * 256 + n]));
    }
    // wl1/wl2 bf16 pairs (first 128 blocks cover kp=0..127)
    if (k < 128) {
        int kp = k, kk = kp * 2, pc = kp & 7;
        int dst = (kk >> 5) * 4096 + ((kk >> 4) & 1) * 2048 + n * 8 + (pc & 3) * 2 + (pc >> 2);
        g_wt1[dst] = f2bf2(wl1[kk * 256 + n], wl1[(kk + 1) * 256 + n]);
        g_wt2[dst] = f2bf2(wl2[kk * 256 + n], wl2[(kk + 1) * 256 + n]);
    }
}

// ---------------------------------------------------------------------------
// prologue tf32 GEMM core
// ---------------------------------------------------------------------------
__device__ __forceinline__ void prefB32(uint32_t sdst, const float* gsrc, int tid) {
#pragma unroll
    for (int i = 0; i < 8; i++) {
        int off = (tid + i * 256) * 16;
        cp_async16(sdst + off, (const char*)gsrc + off);
    }
    cp_commit();
}

__device__ __forceinline__ void run_gemm_tf(uint32_t sbase, const float* gw,
                                            float acc[4][4], int warp, int lane, int tid) {
    int quad = lane >> 2, q = lane & 3;
#pragma unroll
    for (int t = 0; t < 4; t++)
#pragma unroll
        for (int j = 0; j < 4; j++) acc[t][j] = 0.f;
    uint32_t aBase = sbase + P_AST + (uint32_t)(quad * 32 + q * 8);
    uint32_t bBase = (uint32_t)(warp * 1024 + quad * 32 + q * 8);
    for (int p = 0; p < 8; p++) {
        if (p < 7) {
            prefB32(sbase + (((p + 1) & 1) ? P_W1 : P_W0), gw + (p + 1) * 8192, tid);
            cp_wait1();
        } else {
            cp_wait0();
        }
        __syncthreads();
        uint32_t wb = sbase + ((p & 1) ? P_W1 : P_W0) + bBase;
#pragma unroll
        for (int kc4 = 0; kc4 < 4; kc4++) {
            int kcg = p * 4 + kc4;
            uint32_t a0, a1, a2, a3;
            lds2u(aBase + kcg * 512, a0, a2);
            lds2u(aBase + kcg * 512 + 256, a1, a3);
            uint32_t bb = wb + kc4 * 8192;
#pragma unroll
            for (int t = 0; t < 4; t++) {
                uint32_t b0, b1;
                lds2u(bb + t * 256, b0, b1);
                mma_tf(acc[t][0], acc[t][1], acc[t][2], acc[t][3], a0, a1, a2, a3, b0, b1);
            }
        }
    }
}

// ---------------------------------------------------------------------------
// K1: qkv via tf32 mma
// ---------------------------------------------------------------------------
__global__ void __launch_bounds__(256, 1)
qkv_mma_kernel(const float* __restrict__ x, const float* __restrict__ bqkv) {
    extern __shared__ __align__(16) float smF[];
    uint32_t sbase;
    asm("{ .reg .u64 t; cvta.to.shared.u64 t, %1; cvt.u32.u64 %0, t; }"
        : "=r"(sbase) : "l"((const void*)smF));
    int tid = threadIdx.x, warp = tid >> 5, lane = tid & 31;
    int r0 = blockIdx.x * 16, g = blockIdx.y;

    for (int idx = tid; idx < 16 * 256; idx += 256) {
        int r = idx >> 8, c = idx & 255;
        sts1u(sbase + astf(r, c), f2tf(x[(r0 + r) * 256 + c]));
    }
    prefB32(sbase + P_W0, g_wqkv_t + g * 65536, tid);

    float acc[4][4];
    run_gemm_tf(sbase, g_wqkv_t + g * 65536, acc, warp, lane, tid);

    int quad = lane >> 2, q = lane & 3;
#pragma unroll
    for (int t = 0; t < 4; t++) {
        int cb = warp * 32 + t * 8 + q * 2;
        float2 bias = *(const float2*)(bqkv + g * 256 + cb);
        int h = cb >> 5, d = cb & 31;
#pragma unroll
        for (int half = 0; half < 2; half++) {
            int r = r0 + quad + half * 8;
            int b = r >> 8, n = r & 255;
            float2 ov;
            ov.x = acc[t][2 * half + 0] + bias.x;
            ov.y = acc[t][2 * half + 1] + bias.y;
            *(float2*)(g_qbuf + (((g * BDIM + b) * HEADS + h) * NTOK + n) * HD + d) = ov;
        }
    }
}

// ---------------------------------------------------------------------------
// K2: attention — split over query halves (128 CTAs)
// ---------------------------------------------------------------------------
#define ATTN_SMEM ((3 * 256 * 33 + 8 * 256) * 4)
__global__ void attn_kernel() {
    extern __shared__ float sm[];
    float* qs = sm;
    float* ks = qs + 256 * 33;
    float* vs = ks + 256 * 33;
    float* prob = vs + 256 * 33;
    int tid = threadIdx.x, lane = tid & 31, w = tid >> 5;
    int bh = blockIdx.x >> 1, half = blockIdx.x & 1;
    int b = bh >> 3, h = bh & 7;
    const float scale = 0.17677669529663687f;
    const float* qg = g_qbuf + ((0 * BDIM + b) * HEADS + h) * NTOK * HD;
    const float* kg = g_qbuf + ((1 * BDIM + b) * HEADS + h) * NTOK * HD;
    const float* vg = g_qbuf + ((2 * BDIM + b) * HEADS + h) * NTOK * HD;
    for (int idx = tid; idx < NTOK * HD; idx += 256) {
        int n = idx >> 5, d = idx & 31;
        qs[n * 33 + d] = qg[idx] * scale;
        ks[n * 33 + d] = kg[idx];
        vs[n * 33 + d] = vg[idx];
    }
    __syncthreads();
    for (int n = 128 * half + w; n < 128 * (half + 1); n += 8) {
        float s[8];
#pragma unroll
        for (int u = 0; u < 8; u++) {
            int j = lane + 32 * u;
            float a = 0.f;
#pragma unroll 8
            for (int d = 0; d < HD; d++) a = fmaf(qs[n * 33 + d], ks[j * 33 + d], a);
            s[u] = a;
        }
        float mx = s[0];
#pragma unroll
        for (int u = 1; u < 8; u++) mx = fmaxf(mx, s[u]);
#pragma unroll
        for (int o = 16; o > 0; o >>= 1) mx = fmaxf(mx, __shfl_xor_sync(0xffffffffu, mx, o));
        float sum = 0.f;
#pragma unroll
        for (int u = 0; u < 8; u++) { s[u] = __expf(s[u] - mx); sum += s[u]; }
#pragma unroll
        for (int o = 16; o > 0; o >>= 1) sum += __shfl_xor_sync(0xffffffffu, sum, o);
        float inv = 1.f / sum;
#pragma unroll
        for (int u = 0; u < 8; u++) prob[w * 256 + lane + 32 * u] = s[u] * inv;
        __syncwarp();
        float acc = 0.f;
#pragma unroll 8
        for (int j = 0; j < NTOK; j++) acc = fmaf(prob[w * 256 + j], vs[j * 33 + lane], acc);
        g_attnout[(b * NTOK + n) * CDIM + h * HD + lane] = acc;
        __syncwarp();
    }
}

// ---------------------------------------------------------------------------
// K3: x1 = LN(x + attnout @ wo + bo) via tf32 mma
// ---------------------------------------------------------------------------
__global__ void __launch_bounds__(256, 1)
proj_mma_kernel(const float* __restrict__ x, const float* __restrict__ bo,
                const float* __restrict__ g1, const float* __restrict__ b1) {
    extern __shared__ __align__(16) float smF[];
    uint32_t sbase;
    asm("{ .reg .u64 t; cvta.to.shared.u64 t, %1; cvt.u32.u64 %0, t; }"
        : "=r"(sbase) : "l"((const void*)smF));
    int tid = threadIdx.x, warp = tid >> 5, lane = tid & 31;
    int r0 = blockIdx.x * 16;

    for (int idx = tid; idx < 16 * 256; idx += 256) {
        int r = idx >> 8, c = idx & 255;
        sts1u(sbase + astf(r, c), f2tf(g_attnout[(r0 + r) * 256 + c]));
    }
    prefB32(sbase + P_W0, g_wo_t, tid);

    float acc[4][4];
    run_gemm_tf(sbase, g_wo_t, acc, warp, lane, tid);

    float* red = smF + P_RED / 4;
    float* stt = smF + P_STAT / 4;
    int quad = lane >> 2, q = lane & 3;
    float v[4][4];
    float sl = 0.f, sh = 0.f, ql = 0.f, qh = 0.f;
#pragma unroll
    for (int t = 0; t < 4; t++) {
        int cb = warp * 32 + t * 8 + q * 2;
        float2 bias = *(const float2*)(bo + cb);
        float2 rlo = *(const float2*)(x + (r0 + quad) * 256 + cb);
        float2 rhi = *(const float2*)(x + (r0 + quad + 8) * 256 + cb);
        float v00 = acc[t][0] + bias.x + rlo.x, v01 = acc[t][1] + bias.y + rlo.y;
        float v10 = acc[t][2] + bias.x + rhi.x, v11 = acc[t][3] + bias.y + rhi.y;
        v[t][0] = v00; v[t][1] = v01; v[t][2] = v10; v[t][3] = v11;
        sl += v00 + v01; ql += v00 * v00 + v01 * v01;
        sh += v10 + v11; qh += v10 * v10 + v11 * v11;
    }
#pragma unroll
    for (int o = 1; o < 4; o <<= 1) {
        sl += __shfl_xor_sync(0xffffffffu, sl, o);
        sh += __shfl_xor_sync(0xffffffffu, sh, o);
        ql += __shfl_xor_sync(0xffffffffu, ql, o);
        qh += __shfl_xor_sync(0xffffffffu, qh, o);
    }
    if (q == 0) {
        red[warp * 16 + quad] = sl;
        red[warp * 16 + quad + 8] = sh;
        red[128 + warp * 16 + quad] = ql;
        red[128 + warp * 16 + quad + 8] = qh;
    }
    __syncthreads();
    if (tid < 16) {
        float ts = 0.f, tq = 0.f;
#pragma unroll
        for (int w = 0; w < 8; w++) { ts += red[w * 16 + tid]; tq += red[128 + w * 16 + tid]; }
        float mean = ts * (1.f / 256.f);
        float rstd = rsqrtf(tq * (1.f / 256.f) - mean * mean + EPSLN);
        stt[tid] = rstd; stt[16 + tid] = -mean * rstd;
    }
    __syncthreads();
    float Al = stt[quad], Bl = stt[16 + quad];
    float Ah = stt[quad + 8], Bh = stt[16 + quad + 8];
#pragma unroll
    for (int t = 0; t < 4; t++) {
        int cb = warp * 32 + t * 8 + q * 2;
        float2 gg = *(const float2*)(g1 + cb);
        float2 nn = *(const float2*)(b1 + cb);
        float2 olo, ohi;
        olo.x = (v[t][0] * Al + Bl) * gg.x + nn.x;
        olo.y = (v[t][1] * Al + Bl) * gg.y + nn.y;
        ohi.x = (v[t][2] * Ah + Bh) * gg.x + nn.x;
        ohi.y = (v[t][3] * Ah + Bh) * gg.y + nn.y;
        *(float2*)(g_x1 + (r0 + quad) * 256 + cb) = olo;
        *(float2*)(g_x1 + (r0 + quad + 8) * 256 + cb) = ohi;
    }
}

// ---------------------------------------------------------------------------
// ODE kernel: W1 resident; W2 3-buffer ring; k1-3 global (loads hoisted
// before LN barriers); fused output LN at the tail.
// ---------------------------------------------------------------------------
__device__ __forceinline__ void prefB(uint32_t sdst, const uint32_t* gsrc, int tid) {
#pragma unroll
    for (int i = 0; i < 4; i++) {
        int off = (tid + i * 256) * 16;
        cp_async16(sdst + off, (const char*)gsrc + off);
    }
    cp_commit();
}

// GEMM1: W1 resident — no waits, no barriers
__device__ __forceinline__ void run_gemm1(uint32_t sbase, float acc[4][4], int warp, int lane) {
    int quad = lane >> 2, q = lane & 3;
#pragma unroll
    for (int t = 0; t < 4; t++)
#pragma unroll
        for (int j = 0; j < 4; j++) acc[t][j] = 0.f;
    uint32_t aBase = sbase + OFF_AST + (uint32_t)(quad * 32 + q * 8);
    uint32_t bBase = (uint32_t)((warp * 32 + quad) * 32 + q * 8);
#pragma unroll 2
    for (int p = 0; p < 8; p++) {
        uint32_t wb = sbase + OFF_W1R + p * 16384 + bBase;
#pragma unroll
        for (int cc = 0; cc < 2; cc++) {
            int c = p * 2 + cc;
            uint32_t a0, a1, a2, a3;
            lds2u(aBase + c * 512, a0, a2);
            lds2u(aBase + c * 512 + 256, a1, a3);
            uint32_t bb = wb + cc * 8192;
#pragma unroll
            for (int t = 0; t < 4; t++) {
                uint32_t b0, b1;
                lds2u(bb + t * 256, b0, b1);
                mma_bf(acc[t][0], acc[t][1], acc[t][2], acc[t][3], a0, a1, a2, a3, b0, b1);
            }
        }
    }
}

// GEMM2: W2 streamed, 3-buffer ring (prefetch after barrier: race-free)
__device__ __forceinline__ void run_gemm2(uint32_t sbase, float acc[4][4],
                                          int warp, int lane, int tid) {
    int quad = lane >> 2, q = lane & 3;
#pragma unroll
    for (int t = 0; t < 4; t++)
#pragma unroll
        for (int j = 0; j < 4; j++) acc[t][j] = 0.f;
    uint32_t aBase = sbase + OFF_AST + (uint32_t)(quad * 32 + q * 8);
    uint32_t bBase = (uint32_t)((warp * 32 + quad) * 32 + q * 8);
    const uint32_t W2B[3] = { OFF_W20, OFF_W21, OFF_W22 };
    for (int p = 0; p < 8; p++) {
        if (p < 7) cp_wait1(); else cp_wait0();
        __syncthreads();
        if (p < 6) prefB(sbase + W2B[(p + 2) % 3], g_wt2 + (p + 2) * 4096, tid);
        uint32_t wb = sbase + W2B[p % 3] + bBase;
#pragma unroll
        for (int cc = 0; cc < 2; cc++) {
            int c = p * 2 + cc;
            uint32_t a0, a1, a2, a3;
            lds2u(aBase + c * 512, a0, a2);
            lds2u(aBase + c * 512 + 256, a1, a3);
            uint32_t bb = wb + cc * 8192;
#pragma unroll
            for (int t = 0; t < 4; t++) {
                uint32_t b0, b1;
                lds2u(bb + t * 256, b0, b1);
                mma_bf(acc[t][0], acc[t][1], acc[t][2], acc[t][3], a0, a1, a2, a3, b0, b1);
            }
        }
    }
}

template <int ST>
__device__ __forceinline__ void epi2(float* smF, uint32_t sbase, float acc[4][4],
                                     int warp, int lane, int tid, int r0) {
    int quad = lane >> 2, q = lane & 3;
    float* RES = smF + ((ST == 0) ? OFF_YS : OFF_AR) / 4;
    float* CST = smF + OFF_CST / 4;
    float* red = smF + OFF_RED / 4;
    float* stt = smF + OFF_STAT / 4;
    float v[4][4];
    float sl = 0.f, sh = 0.f, ql = 0.f, qh = 0.f;
#pragma unroll
    for (int t = 0; t < 4; t++) {
        int cb = warp * 32 + t * 8 + q * 2;
        float2 bias = *(float2*)(CST + 256 + cb);
        float2 rlo = *(float2*)(RES + quad * RMJ + cb);
        float2 rhi = *(float2*)(RES + (quad + 8) * RMJ + cb);
        float v00 = acc[t][0] + bias.x + rlo.x, v01 = acc[t][1] + bias.y + rlo.y;
        float v10 = acc[t][2] + bias.x + rhi.x, v11 = acc[t][3] + bias.y + rhi.y;
        v[t][0] = v00; v[t][1] = v01; v[t][2] = v10; v[t][3] = v11;
        sl += v00 + v01; ql += v00 * v00 + v01 * v01;
        sh += v10 + v11; qh += v10 * v10 + v11 * v11;
    }
    // ---- hoisted global k loads: issue BEFORE the LN barriers so the L2
    //      latency drains underneath the reduction/stat work ----
    float2 k1l[4], k1h[4], k2l[4], k2h[4], k3l[4], k3h[4];
    if (ST >= 1) {
#pragma unroll
        for (int t = 0; t < 4; t++) {
            int cb = warp * 32 + t * 8 + q * 2;
            int gl = (r0 + quad) * 256 + cb;
            k1l[t] = *(const float2*)(g_k1 + gl);
            k1h[t] = *(const float2*)(g_k1 + gl + 2048);
            if (ST >= 2) {
                k2l[t] = *(const float2*)(g_k2 + gl);
                k2h[t] = *(const float2*)(g_k2 + gl + 2048);
            }
            if (ST == 3) {
                k3l[t] = *(const float2*)(g_k3 + gl);
                k3h[t] = *(const float2*)(g_k3 + gl + 2048);
            }
        }
    }
#pragma unroll
    for (int o = 1; o < 4; o <<= 1) {
        sl += __shfl_xor_sync(0xffffffffu, sl, o);
        sh += __shfl_xor_sync(0xffffffffu, sh, o);
        ql += __shfl_xor_sync(0xffffffffu, ql, o);
        qh += __shfl_xor_sync(0xffffffffu, qh, o);
    }
    if (q == 0) {
        red[warp * 16 + quad] = sl;
        red[warp * 16 + quad + 8] = sh;
        red[128 + warp * 16 + quad] = ql;
        red[128 + warp * 16 + quad + 8] = qh;
    }
    __syncthreads();
    if (tid < 16) {
        float ts = 0.f, tq = 0.f;
#pragma unroll
        for (int w = 0; w < 8; w++) { ts += red[w * 16 + tid]; tq += red[128 + w * 16 + tid]; }
        float mean = ts * (1.f / 256.f);
        float rstd = rsqrtf(tq * (1.f / 256.f) - mean * mean + EPSLN);
        stt[tid] = rstd; stt[16 + tid] = -mean * rstd;
    }
    __syncthreads();
    float Al = stt[quad], Bl = stt[16 + quad];
    float Ah = stt[quad + 8], Bh = stt[16 + quad + 8];
    float* Y  = smF + OFF_YS / 4;
    float* AR = smF + OFF_AR / 4;
#pragma unroll
    for (int t = 0; t < 4; t++) {
        int cb = warp * 32 + t * 8 + q * 2;
        int ol = quad * RMJ + cb, oh = (quad + 8) * RMJ + cb;
        int gl = (r0 + quad) * 256 + cb, gh = (r0 + quad + 8) * 256 + cb;
        float2 gg = *(float2*)(CST + 512 + cb);
        float2 nn = *(float2*)(CST + 768 + cb);
        float k00 = (v[t][0] * Al + Bl) * gg.x + nn.x;
        float k01 = (v[t][1] * Al + Bl) * gg.y + nn.y;
        float k10 = (v[t][2] * Ah + Bh) * gg.x + nn.x;
        float k11 = (v[t][3] * Ah + Bh) * gg.y + nn.y;
        float2 ylo = *(float2*)(Y + ol), yhi = *(float2*)(Y + oh);
        float a00, a01, a10, a11;
        if (ST == 0) {
            *(float2*)(g_k1 + gl) = make_float2(k00, k01);
            *(float2*)(g_k1 + gh) = make_float2(k10, k11);
            const float c3 = DT * (1.f / 3.f);
            a00 = ylo.x + c3 * k00; a01 = ylo.y + c3 * k01;
            a10 = yhi.x + c3 * k10; a11 = yhi.y + c3 * k11;
        } else if (ST == 1) {
            *(float2*)(g_k2 + gl) = make_float2(k00, k01);
            *(float2*)(g_k2 + gh) = make_float2(k10, k11);
            a00 = ylo.x + DT * (k00 - (1.f / 3.f) * k1l[t].x);
            a01 = ylo.y + DT * (k01 - (1.f / 3.f) * k1l[t].y);
            a10 = yhi.x + DT * (k10 - (1.f / 3.f) * k1h[t].x);
            a11 = yhi.y + DT * (k11 - (1.f / 3.f) * k1h[t].y);
        } else if (ST == 2) {
            *(float2*)(g_k3 + gl) = make_float2(k00, k01);
            *(float2*)(g_k3 + gh) = make_float2(k10, k11);
            a00 = ylo.x + DT * (k1l[t].x - k2l[t].x + k00);
            a01 = ylo.y + DT * (k1l[t].y - k2l[t].y + k01);
            a10 = yhi.x + DT * (k1h[t].x - k2h[t].x + k10);
            a11 = yhi.y + DT * (k1h[t].y - k2h[t].y + k11);
        } else {
            a00 = ylo.x + (DT * 0.125f) * (k1l[t].x + 3.f * (k2l[t].x + k3l[t].x) + k00);
            a01 = ylo.y + (DT * 0.125f) * (k1l[t].y + 3.f * (k2l[t].y + k3l[t].y) + k01);
            a10 = yhi.x + (DT * 0.125f) * (k1h[t].x + 3.f * (k2h[t].x + k3h[t].x) + k10);
            a11 = yhi.y + (DT * 0.125f) * (k1h[t].y + 3.f * (k2h[t].y + k3h[t].y) + k11);
        }
        if (ST < 3) {
            *(float2*)(AR + ol) = make_float2(a00, a01);
            *(float2*)(AR + oh) = make_float2(a10, a11);
        } else {
            *(float2*)(Y + ol) = make_float2(a00, a01);
            *(float2*)(Y + oh) = make_float2(a10, a11);
        }
        sts1u(sbase + astb2(quad, cb), f2bf2(a00, a01));
        sts1u(sbase + astb2(quad + 8, cb), f2bf2(a10, a11));
    }
}

__global__ void __launch_bounds__(256, 1)
ode_mma_kernel(const int* __restrict__ lead, const int* __restrict__ nsp,
               const float* __restrict__ bl1, const float* __restrict__ bl2,
               const float* __restrict__ gn, const float* __restrict__ bn,
               const float* __restrict__ g2, const float* __restrict__ b2,
               float* __restrict__ out) {
    extern __shared__ __align__(16) float smF[];
    uint32_t sbase;
    asm("{ .reg .u64 t; cvta.to.shared.u64 t, %1; cvt.u32.u64 %0, t; }"
        : "=r"(sbase) : "l"((const void*)smF));
    int tid = threadIdx.x, warp = tid >> 5, lane = tid & 31;
    int r0 = blockIdx.x * 16;
    int steps = lead[r0 >> 8];
    int ns = nsp ? nsp[0] : 50;
    if (steps > ns) steps = ns;
    if (steps < 0) steps = 0;

    // load W1 resident (one cp.async group)
#pragma unroll
    for (int i = 0; i < 32; i++) {
        int off = (tid + i * 256) * 16;
        cp_async16(sbase + OFF_W1R + off, (const char*)g_wt1 + off);
    }
    cp_commit();

    float* CST = smF + OFF_CST / 4;
    for (int i = tid; i < 256; i += 256) {
        CST[i] = bl1[i]; CST[256 + i] = bl2[i];
        CST[512 + i] = gn[i]; CST[768 + i] = bn[i];
    }
    for (int idx = tid; idx < 16 * 128; idx += 256) {
        int r = idx >> 7, kp = idx & 127;
        int cb = kp * 2;
        float2 vv = *(const float2*)(g_x1 + (r0 + r) * 256 + cb);
        smF[OFF_YS / 4 + r * RMJ + cb] = vv.x;
        smF[OFF_YS / 4 + r * RMJ + cb + 1] = vv.y;
        sts1u(sbase + astb2(r, cb), f2bf2(vv.x, vv.y));
    }
    cp_wait0();
    __syncthreads();

    float acc[4][4];
    for (int s = 0; s < steps; s++) {
#pragma unroll 1
        for (int st = 0; st < 4; st++) {
            // prime W2 blocks 0,1 (overlaps with GEMM1)
            prefB(sbase + OFF_W20, g_wt2, tid);
            prefB(sbase + OFF_W21, g_wt2 + 4096, tid);
            run_gemm1(sbase, acc, warp, lane);
            __syncthreads();
            // epi1: h1 = relu(acc + bl1) -> A-stage (bf16)
            {
                int quad = lane >> 2, q = lane & 3;
#pragma unroll
                for (int t = 0; t < 4; t++) {
                    int cb = warp * 32 + t * 8 + q * 2;
                    float2 bias = *(float2*)(CST + cb);
                    sts1u(sbase + astb2(quad, cb),
                          f2bf2(fmaxf(acc[t][0] + bias.x, 0.f), fmaxf(acc[t][1] + bias.y, 0.f)));
                    sts1u(sbase + astb2(quad + 8, cb),
                          f2bf2(fmaxf(acc[t][2] + bias.x, 0.f), fmaxf(acc[t][3] + bias.y, 0.f)));
                }
            }
            // GEMM2's internal first wait+sync publishes epi1 stores
            run_gemm2(sbase, acc, warp, lane, tid);
            if (st == 0)      epi2<0>(smF, sbase, acc, warp, lane, tid, r0);
            else if (st == 1) epi2<1>(smF, sbase, acc, warp, lane, tid, r0);
            else if (st == 2) epi2<2>(smF, sbase, acc, warp, lane, tid, r0);
            else              epi2<3>(smF, sbase, acc, warp, lane, tid, r0);
            __syncthreads();
        }
    }
    cp_wait0();
    __syncthreads();

    // ---- fused output LN: out = LN(x1 + ys; g2, b2) ----
#pragma unroll
    for (int rr = 0; rr < 2; rr++) {
        int r = warp * 2 + rr;
        float v[8], ls = 0.f, lq = 0.f;
#pragma unroll
        for (int u = 0; u < 8; u++) {
            int c = lane + 32 * u;
            float t = g_x1[(r0 + r) * 256 + c] + smF[OFF_YS / 4 + r * RMJ + c];
            v[u] = t; ls += t; lq += t * t;
        }
#pragma unroll
        for (int o = 16; o > 0; o >>= 1) {
            ls += __shfl_xor_sync(0xffffffffu, ls, o);
            lq += __shfl_xor_sync(0xffffffffu, lq, o);
        }
        float mean = ls * (1.f / 256.f);
        float rstd = rsqrtf(lq * (1.f / 256.f) - mean * mean + EPSLN);
#pragma unroll
        for (int u = 0; u < 8; u++) {
            int c = lane + 32 * u;
            out[(r0 + r) * 256 + c] = (v[u] - mean) * rstd * g2[c] + b2[c];
        }
    }
}

// ---------------------------------------------------------------------------
// Launch
// ---------------------------------------------------------------------------
extern "C" void kernel_launch(void* const* d_in, const int* in_sizes, int n_in,
                              void* d_out, int out_size) {
    const float* x    = (const float*)d_in[0];
    const float* wqkv = (const float*)d_in[1];
    const float* bqkv = (const float*)d_in[2];
    const float* wo   = (const float*)d_in[3];
    const float* bo   = (const float*)d_in[4];
    const float* g1   = (const float*)d_in[5];
    const float* b1   = (const float*)d_in[6];
    const float* g2   = (const float*)d_in[7];
    const float* b2   = (const float*)d_in[8];
    const float* wl1  = (const float*)d_in[9];
    const float* bl1  = (const float*)d_in[10];
    const float* wl2  = (const float*)d_in[11];
    const float* bl2  = (const float*)d_in[12];
    const float* gn   = (const float*)d_in[13];
    const float* bn   = (const float*)d_in[14];
    const int* lead   = (const int*)d_in[15];
    const int* nsteps = (n_in > 16) ? (const int*)d_in[16] : nullptr;
    float* out = (float*)d_out;

    cudaFuncSetAttribute(attn_kernel, cudaFuncAttributeMaxDynamicSharedMemorySize, ATTN_SMEM);
    cudaFuncSetAttribute(ode_mma_kernel, cudaFuncAttributeMaxDynamicSharedMemorySize, ODE_SMEM);
    cudaFuncSetAttribute(qkv_mma_kernel, cudaFuncAttributeMaxDynamicSharedMemorySize, QKV_SMEM);
    cudaFuncSetAttribute(proj_mma_kernel, cudaFuncAttributeMaxDynamicSharedMemorySize, PROJ_SMEM);

    prep_all_kernel<<<256, 256>>>(wl1, wl2, wqkv, wo);
    qkv_mma_kernel<<<dim3(128, 3), 256, QKV_SMEM>>>(x, bqkv);
    attn_kernel<<<128, 256, ATTN_SMEM>>>();
    proj_mma_kernel<<<128, 256, PROJ_SMEM>>>(x, bo, g1, b1);
    ode_mma_kernel<<<128, 256, ODE_SMEM>>>(lead, nsteps, bl1, bl2, gn, bn, g2, b2, out);
}

// round 17
// speedup vs baseline: 2.7088x; 1.2098x over previous
#include <cuda_runtime.h>
#include <math.h>
#include <stdint.h>

#define EPSLN 1e-5f
#define DT    0.01f
#define CDIM  256
#define BDIM  8
#define NTOK  256
#define HEADS 8
#define HD    32
#define ROWS  (BDIM * NTOK)

// ---- ODE smem layout (bytes) ----
#define OFF_AST  0          // 8192 (bf16 A-stage)
#define OFF_W1R  8192       // 131072 (W1 resident, bf16 MMA-B layout)
#define OFF_W2   139264     // 65536 (4-buffer W2 ring)
#define OFF_RED  204800     // 1024
#define OFF_STAT 205824     // 128
#define OFF_CST  205952     // 4096
#define ODE_SMEM 210048

// ---- prologue mma kernels smem layout (bytes) ----
#define P_AST    0          // 16 KB tf32 A-stage
#define P_W0     16384      // 32 KB
#define P_W1     49152      // 32 KB
#define P_RED    81920      // 256 floats
#define P_STAT   82944      // 32 floats
#define QKV_SMEM 81920
#define PROJ_SMEM 83072

// ---------------------------------------------------------------------------
// Scratch globals
// ---------------------------------------------------------------------------
__device__ float g_qbuf[3 * BDIM * HEADS * NTOK * HD];
__device__ float g_attnout[ROWS * CDIM];
__device__ float g_x1[ROWS * CDIM];
// bf16-pair ODE weights in MMA-B layout
__device__ uint32_t g_wt1[CDIM * CDIM / 2];
__device__ uint32_t g_wt2[CDIM * CDIM / 2];
// tf32 MMA-B layout prologue weights
__device__ float g_wqkv_t[CDIM * 768];
__device__ float g_wo_t[CDIM * CDIM];

// ---------------------------------------------------------------------------
// helpers
// ---------------------------------------------------------------------------
__device__ __forceinline__ uint32_t f2bf2(float lo, float hi) {
    uint32_t r; asm("cvt.rn.bf16x2.f32 %0, %1, %2;" : "=r"(r) : "f"(hi), "f"(lo)); return r;
}
__device__ __forceinline__ uint32_t f2tf(float f) {
    uint32_t r; asm("cvt.rna.tf32.f32 %0, %1;" : "=r"(r) : "f"(f)); return r;
}
__device__ __forceinline__ void lds2u(uint32_t a, uint32_t& x, uint32_t& y) {
    asm volatile("ld.shared.v2.b32 {%0,%1}, [%2];" : "=r"(x), "=r"(y) : "r"(a));
}
__device__ __forceinline__ void sts1u(uint32_t a, uint32_t v) {
    asm volatile("st.shared.b32 [%0], %1;" :: "r"(a), "r"(v));
}
__device__ __forceinline__ void cp_async16(uint32_t sdst, const void* gsrc) {
    asm volatile("cp.async.cg.shared.global [%0], [%1], 16;" :: "r"(sdst), "l"(gsrc));
}
__device__ __forceinline__ void cp_commit() { asm volatile("cp.async.commit_group;"); }
__device__ __forceinline__ void cp_wait1() { asm volatile("cp.async.wait_group 1;" ::: "memory"); }
__device__ __forceinline__ void cp_wait0() { asm volatile("cp.async.wait_group 0;" ::: "memory"); }

__device__ __forceinline__ void mma_bf(float& c0, float& c1, float& c2, float& c3,
                                       uint32_t a0, uint32_t a1, uint32_t a2, uint32_t a3,
                                       uint32_t b0, uint32_t b1) {
    asm volatile(
        "mma.sync.aligned.m16n8k16.row.col.f32.bf16.bf16.f32 "
        "{%0,%1,%2,%3},{%4,%5,%6,%7},{%8,%9},{%0,%1,%2,%3};"
        : "+f"(c0), "+f"(c1), "+f"(c2), "+f"(c3)
        : "r"(a0), "r"(a1), "r"(a2), "r"(a3), "r"(b0), "r"(b1));
}
__device__ __forceinline__ void mma_tf(float& c0, float& c1, float& c2, float& c3,
                                       uint32_t a0, uint32_t a1, uint32_t a2, uint32_t a3,
                                       uint32_t b0, uint32_t b1) {
    asm volatile(
        "mma.sync.aligned.m16n8k8.row.col.f32.tf32.tf32.f32 "
        "{%0,%1,%2,%3},{%4,%5,%6,%7},{%8,%9},{%0,%1,%2,%3};"
        : "+f"(c0), "+f"(c1), "+f"(c2), "+f"(c3)
        : "r"(a0), "r"(a1), "r"(a2), "r"(a3), "r"(b0), "r"(b1));
}

// bf16 A-stage byte offset (ODE)
__device__ __forceinline__ uint32_t astb2(int r, int cb) {
    int pc = (cb >> 1) & 7;
    return OFF_AST + (uint32_t)((cb >> 4) * 512 + r * 32 + ((pc & 3) * 2 + (pc >> 2)) * 4);
}
// tf32 A-stage byte offset (prologue)
__device__ __forceinline__ uint32_t astf(int r, int c) {
    return P_AST + (uint32_t)((c >> 3) * 512 + r * 32 + (c & 3) * 8 + ((c >> 2) & 1) * 4);
}

// ---------------------------------------------------------------------------
// fused prep kernel
// ---------------------------------------------------------------------------
__global__ void prep_all_kernel(const float* __restrict__ wl1, const float* __restrict__ wl2,
                                const float* __restrict__ wqkv, const float* __restrict__ wo) {
    int k = blockIdx.x, n = threadIdx.x;
    {
        int dst = (k >> 5) * 8192 + ((k >> 3) & 3) * 2048 + n * 8 + (k & 3) * 2 + ((k >> 2) & 1);
        g_wo_t[dst] = __uint_as_float(f2tf(wo[k * 256 + n]));
#pragma unroll
        for (int g = 0; g < 3; g++)
            g_wqkv_t[g * 65536 + dst] = __uint_as_float(f2tf(wqkv[k * 768 + g * 256 + n]));
    }
    if (k < 128) {
        int kp = k, kk = kp * 2, pc = kp & 7;
        int dst = (kk >> 5) * 4096 + ((kk >> 4) & 1) * 2048 + n * 8 + (pc & 3) * 2 + (pc >> 2);
        g_wt1[dst] = f2bf2(wl1[kk * 256 + n], wl1[(kk + 1) * 256 + n]);
        g_wt2[dst] = f2bf2(wl2[kk * 256 + n], wl2[(kk + 1) * 256 + n]);
    }
}

// ---------------------------------------------------------------------------
// prologue tf32 GEMM core
// ---------------------------------------------------------------------------
__device__ __forceinline__ void prefB32(uint32_t sdst, const float* gsrc, int tid) {
#pragma unroll
    for (int i = 0; i < 8; i++) {
        int off = (tid + i * 256) * 16;
        cp_async16(sdst + off, (const char*)gsrc + off);
    }
    cp_commit();
}

__device__ __forceinline__ void run_gemm_tf(uint32_t sbase, const float* gw,
                                            float acc[4][4], int warp, int lane, int tid) {
    int quad = lane >> 2, q = lane & 3;
#pragma unroll
    for (int t = 0; t < 4; t++)
#pragma unroll
        for (int j = 0; j < 4; j++) acc[t][j] = 0.f;
    uint32_t aBase = sbase + P_AST + (uint32_t)(quad * 32 + q * 8);
    uint32_t bBase = (uint32_t)(warp * 1024 + quad * 32 + q * 8);
    for (int p = 0; p < 8; p++) {
        if (p < 7) {
            prefB32(sbase + (((p + 1) & 1) ? P_W1 : P_W0), gw + (p + 1) * 8192, tid);
            cp_wait1();
        } else {
            cp_wait0();
        }
        __syncthreads();
        uint32_t wb = sbase + ((p & 1) ? P_W1 : P_W0) + bBase;
#pragma unroll
        for (int kc4 = 0; kc4 < 4; kc4++) {
            int kcg = p * 4 + kc4;
            uint32_t a0, a1, a2, a3;
            lds2u(aBase + kcg * 512, a0, a2);
            lds2u(aBase + kcg * 512 + 256, a1, a3);
            uint32_t bb = wb + kc4 * 8192;
#pragma unroll
            for (int t = 0; t < 4; t++) {
                uint32_t b0, b1;
                lds2u(bb + t * 256, b0, b1);
                mma_tf(acc[t][0], acc[t][1], acc[t][2], acc[t][3], a0, a1, a2, a3, b0, b1);
            }
        }
    }
}

// ---------------------------------------------------------------------------
// K1: qkv via tf32 mma
// ---------------------------------------------------------------------------
__global__ void __launch_bounds__(256, 1)
qkv_mma_kernel(const float* __restrict__ x, const float* __restrict__ bqkv) {
    extern __shared__ __align__(16) float smF[];
    uint32_t sbase;
    asm("{ .reg .u64 t; cvta.to.shared.u64 t, %1; cvt.u32.u64 %0, t; }"
        : "=r"(sbase) : "l"((const void*)smF));
    int tid = threadIdx.x, warp = tid >> 5, lane = tid & 31;
    int r0 = blockIdx.x * 16, g = blockIdx.y;

    for (int idx = tid; idx < 16 * 256; idx += 256) {
        int r = idx >> 8, c = idx & 255;
        sts1u(sbase + astf(r, c), f2tf(x[(r0 + r) * 256 + c]));
    }
    prefB32(sbase + P_W0, g_wqkv_t + g * 65536, tid);

    float acc[4][4];
    run_gemm_tf(sbase, g_wqkv_t + g * 65536, acc, warp, lane, tid);

    int quad = lane >> 2, q = lane & 3;
#pragma unroll
    for (int t = 0; t < 4; t++) {
        int cb = warp * 32 + t * 8 + q * 2;
        float2 bias = *(const float2*)(bqkv + g * 256 + cb);
        int h = cb >> 5, d = cb & 31;
#pragma unroll
        for (int half = 0; half < 2; half++) {
            int r = r0 + quad + half * 8;
            int b = r >> 8, n = r & 255;
            float2 ov;
            ov.x = acc[t][2 * half + 0] + bias.x;
            ov.y = acc[t][2 * half + 1] + bias.y;
            *(float2*)(g_qbuf + (((g * BDIM + b) * HEADS + h) * NTOK + n) * HD + d) = ov;
        }
    }
}

// ---------------------------------------------------------------------------
// K2: attention — split over query halves (128 CTAs)
// ---------------------------------------------------------------------------
#define ATTN_SMEM ((3 * 256 * 33 + 8 * 256) * 4)
__global__ void attn_kernel() {
    extern __shared__ float sm[];
    float* qs = sm;
    float* ks = qs + 256 * 33;
    float* vs = ks + 256 * 33;
    float* prob = vs + 256 * 33;
    int tid = threadIdx.x, lane = tid & 31, w = tid >> 5;
    int bh = blockIdx.x >> 1, half = blockIdx.x & 1;
    int b = bh >> 3, h = bh & 7;
    const float scale = 0.17677669529663687f;
    const float* qg = g_qbuf + ((0 * BDIM + b) * HEADS + h) * NTOK * HD;
    const float* kg = g_qbuf + ((1 * BDIM + b) * HEADS + h) * NTOK * HD;
    const float* vg = g_qbuf + ((2 * BDIM + b) * HEADS + h) * NTOK * HD;
    for (int idx = tid; idx < NTOK * HD; idx += 256) {
        int n = idx >> 5, d = idx & 31;
        qs[n * 33 + d] = qg[idx] * scale;
        ks[n * 33 + d] = kg[idx];
        vs[n * 33 + d] = vg[idx];
    }
    __syncthreads();
    for (int n = 128 * half + w; n < 128 * (half + 1); n += 8) {
        float s[8];
#pragma unroll
        for (int u = 0; u < 8; u++) {
            int j = lane + 32 * u;
            float a = 0.f;
#pragma unroll 8
            for (int d = 0; d < HD; d++) a = fmaf(qs[n * 33 + d], ks[j * 33 + d], a);
            s[u] = a;
        }
        float mx = s[0];
#pragma unroll
        for (int u = 1; u < 8; u++) mx = fmaxf(mx, s[u]);
#pragma unroll
        for (int o = 16; o > 0; o >>= 1) mx = fmaxf(mx, __shfl_xor_sync(0xffffffffu, mx, o));
        float sum = 0.f;
#pragma unroll
        for (int u = 0; u < 8; u++) { s[u] = __expf(s[u] - mx); sum += s[u]; }
#pragma unroll
        for (int o = 16; o > 0; o >>= 1) sum += __shfl_xor_sync(0xffffffffu, sum, o);
        float inv = 1.f / sum;
#pragma unroll
        for (int u = 0; u < 8; u++) prob[w * 256 + lane + 32 * u] = s[u] * inv;
        __syncwarp();
        float acc = 0.f;
#pragma unroll 8
        for (int j = 0; j < NTOK; j++) acc = fmaf(prob[w * 256 + j], vs[j * 33 + lane], acc);
        g_attnout[(b * NTOK + n) * CDIM + h * HD + lane] = acc;
        __syncwarp();
    }
}

// ---------------------------------------------------------------------------
// K3: x1 = LN(x + attnout @ wo + bo) via tf32 mma
// ---------------------------------------------------------------------------
__global__ void __launch_bounds__(256, 1)
proj_mma_kernel(const float* __restrict__ x, const float* __restrict__ bo,
                const float* __restrict__ g1, const float* __restrict__ b1) {
    extern __shared__ __align__(16) float smF[];
    uint32_t sbase;
    asm("{ .reg .u64 t; cvta.to.shared.u64 t, %1; cvt.u32.u64 %0, t; }"
        : "=r"(sbase) : "l"((const void*)smF));
    int tid = threadIdx.x, warp = tid >> 5, lane = tid & 31;
    int r0 = blockIdx.x * 16;

    for (int idx = tid; idx < 16 * 256; idx += 256) {
        int r = idx >> 8, c = idx & 255;
        sts1u(sbase + astf(r, c), f2tf(g_attnout[(r0 + r) * 256 + c]));
    }
    prefB32(sbase + P_W0, g_wo_t, tid);

    float acc[4][4];
    run_gemm_tf(sbase, g_wo_t, acc, warp, lane, tid);

    float* red = smF + P_RED / 4;
    float* stt = smF + P_STAT / 4;
    int quad = lane >> 2, q = lane & 3;
    float v[4][4];
    float sl = 0.f, sh = 0.f, ql = 0.f, qh = 0.f;
#pragma unroll
    for (int t = 0; t < 4; t++) {
        int cb = warp * 32 + t * 8 + q * 2;
        float2 bias = *(const float2*)(bo + cb);
        float2 rlo = *(const float2*)(x + (r0 + quad) * 256 + cb);
        float2 rhi = *(const float2*)(x + (r0 + quad + 8) * 256 + cb);
        float v00 = acc[t][0] + bias.x + rlo.x, v01 = acc[t][1] + bias.y + rlo.y;
        float v10 = acc[t][2] + bias.x + rhi.x, v11 = acc[t][3] + bias.y + rhi.y;
        v[t][0] = v00; v[t][1] = v01; v[t][2] = v10; v[t][3] = v11;
        sl += v00 + v01; ql += v00 * v00 + v01 * v01;
        sh += v10 + v11; qh += v10 * v10 + v11 * v11;
    }
#pragma unroll
    for (int o = 1; o < 4; o <<= 1) {
        sl += __shfl_xor_sync(0xffffffffu, sl, o);
        sh += __shfl_xor_sync(0xffffffffu, sh, o);
        ql += __shfl_xor_sync(0xffffffffu, ql, o);
        qh += __shfl_xor_sync(0xffffffffu, qh, o);
    }
    if (q == 0) {
        red[warp * 16 + quad] = sl;
        red[warp * 16 + quad + 8] = sh;
        red[128 + warp * 16 + quad] = ql;
        red[128 + warp * 16 + quad + 8] = qh;
    }
    __syncthreads();
    if (tid < 16) {
        float ts = 0.f, tq = 0.f;
#pragma unroll
        for (int w = 0; w < 8; w++) { ts += red[w * 16 + tid]; tq += red[128 + w * 16 + tid]; }
        float mean = ts * (1.f / 256.f);
        float rstd = rsqrtf(tq * (1.f / 256.f) - mean * mean + EPSLN);
        stt[tid] = rstd; stt[16 + tid] = -mean * rstd;
    }
    __syncthreads();
    float Al = stt[quad], Bl = stt[16 + quad];
    float Ah = stt[quad + 8], Bh = stt[16 + quad + 8];
#pragma unroll
    for (int t = 0; t < 4; t++) {
        int cb = warp * 32 + t * 8 + q * 2;
        float2 gg = *(const float2*)(g1 + cb);
        float2 nn = *(const float2*)(b1 + cb);
        float2 olo, ohi;
        olo.x = (v[t][0] * Al + Bl) * gg.x + nn.x;
        olo.y = (v[t][1] * Al + Bl) * gg.y + nn.y;
        ohi.x = (v[t][2] * Ah + Bh) * gg.x + nn.x;
        ohi.y = (v[t][3] * Ah + Bh) * gg.y + nn.y;
        *(float2*)(g_x1 + (r0 + quad) * 256 + cb) = olo;
        *(float2*)(g_x1 + (r0 + quad + 8) * 256 + cb) = ohi;
    }
}

// ---------------------------------------------------------------------------
// ODE kernel: W1 resident; W2 4-buffer ring (barrier per 2 blocks);
// ALL RK4 state (y, arg, k1-3) register-resident; fused output LN.
// ---------------------------------------------------------------------------
__device__ __forceinline__ void prefW2pair(uint32_t sbase, int pairIdx, int tid) {
    uint32_t dst = sbase + OFF_W2 + (uint32_t)(((2 * pairIdx) & 3) * 16384);
    const uint32_t* src = g_wt2 + 2 * pairIdx * 4096;
#pragma unroll
    for (int i = 0; i < 8; i++) {
        int off = (tid + i * 256) * 16;
        cp_async16(dst + off, (const char*)src + off);
    }
    cp_commit();
}

// GEMM1: W1 resident — no waits, no barriers, fully unrolled
__device__ __forceinline__ void run_gemm1(uint32_t sbase, float acc[4][4], int warp, int lane) {
    int quad = lane >> 2, q = lane & 3;
#pragma unroll
    for (int t = 0; t < 4; t++)
#pragma unroll
        for (int j = 0; j < 4; j++) acc[t][j] = 0.f;
    uint32_t aBase = sbase + OFF_AST + (uint32_t)(quad * 32 + q * 8);
    uint32_t bBase = (uint32_t)((warp * 32 + quad) * 32 + q * 8);
#pragma unroll
    for (int p = 0; p < 8; p++) {
        uint32_t wb = sbase + OFF_W1R + p * 16384 + bBase;
#pragma unroll
        for (int cc = 0; cc < 2; cc++) {
            int c = p * 2 + cc;
            uint32_t a0, a1, a2, a3;
            lds2u(aBase + c * 512, a0, a2);
            lds2u(aBase + c * 512 + 256, a1, a3);
            uint32_t bb = wb + cc * 8192;
#pragma unroll
            for (int t = 0; t < 4; t++) {
                uint32_t b0, b1;
                lds2u(bb + t * 256, b0, b1);
                mma_bf(acc[t][0], acc[t][1], acc[t][2], acc[t][3], a0, a1, a2, a3, b0, b1);
            }
        }
    }
}

// GEMM2: W2 streamed, 4-buffer ring, barrier per 2 blocks
__device__ __forceinline__ void run_gemm2(uint32_t sbase, float acc[4][4],
                                          int warp, int lane, int tid) {
    int quad = lane >> 2, q = lane & 3;
#pragma unroll
    for (int t = 0; t < 4; t++)
#pragma unroll
        for (int j = 0; j < 4; j++) acc[t][j] = 0.f;
    uint32_t aBase = sbase + OFF_AST + (uint32_t)(quad * 32 + q * 8);
    uint32_t bBase = (uint32_t)((warp * 32 + quad) * 32 + q * 8);
    for (int j = 0; j < 4; j++) {
        cp_wait0();
        __syncthreads();
        if (j < 3) prefW2pair(sbase, j + 1, tid);
#pragma unroll
        for (int bb2 = 0; bb2 < 2; bb2++) {
            int blk = 2 * j + bb2;
            uint32_t wb = sbase + OFF_W2 + (uint32_t)((blk & 3) * 16384) + bBase;
#pragma unroll
            for (int cc = 0; cc < 2; cc++) {
                int c = blk * 2 + cc;
                uint32_t a0, a1, a2, a3;
                lds2u(aBase + c * 512, a0, a2);
                lds2u(aBase + c * 512 + 256, a1, a3);
                uint32_t bb = wb + cc * 8192;
#pragma unroll
                for (int t = 0; t < 4; t++) {
                    uint32_t b0, b1;
                    lds2u(bb + t * 256, b0, b1);
                    mma_bf(acc[t][0], acc[t][1], acc[t][2], acc[t][3], a0, a1, a2, a3, b0, b1);
                }
            }
        }
    }
}

// epilogue 2: residual+LN+kv+RK4 combine, all state in registers
template <int ST>
__device__ __forceinline__ void epi2(float* smF, uint32_t sbase, float acc[4][4],
                                     float ys_[4][4], float ar_[4][4],
                                     float k1_[4][4], float k2_[4][4], float k3_[4][4],
                                     int warp, int lane, int tid) {
    int quad = lane >> 2, q = lane & 3;
    float* CST = smF + OFF_CST / 4;
    float* red = smF + OFF_RED / 4;
    float* stt = smF + OFF_STAT / 4;
    float v[4][4];
    float sl = 0.f, sh = 0.f, ql = 0.f, qh = 0.f;
#pragma unroll
    for (int t = 0; t < 4; t++) {
        int cb = warp * 32 + t * 8 + q * 2;
        float2 bias = *(float2*)(CST + 256 + cb);
        float r0v = (ST == 0) ? ys_[t][0] : ar_[t][0];
        float r1v = (ST == 0) ? ys_[t][1] : ar_[t][1];
        float r2v = (ST == 0) ? ys_[t][2] : ar_[t][2];
        float r3v = (ST == 0) ? ys_[t][3] : ar_[t][3];
        float v00 = acc[t][0] + bias.x + r0v, v01 = acc[t][1] + bias.y + r1v;
        float v10 = acc[t][2] + bias.x + r2v, v11 = acc[t][3] + bias.y + r3v;
        v[t][0] = v00; v[t][1] = v01; v[t][2] = v10; v[t][3] = v11;
        sl += v00 + v01; ql += v00 * v00 + v01 * v01;
        sh += v10 + v11; qh += v10 * v10 + v11 * v11;
    }
#pragma unroll
    for (int o = 1; o < 4; o <<= 1) {
        sl += __shfl_xor_sync(0xffffffffu, sl, o);
        sh += __shfl_xor_sync(0xffffffffu, sh, o);
        ql += __shfl_xor_sync(0xffffffffu, ql, o);
        qh += __shfl_xor_sync(0xffffffffu, qh, o);
    }
    if (q == 0) {
        red[warp * 16 + quad] = sl;
        red[warp * 16 + quad + 8] = sh;
        red[128 + warp * 16 + quad] = ql;
        red[128 + warp * 16 + quad + 8] = qh;
    }
    __syncthreads();
    if (tid < 16) {
        float ts = 0.f, tq = 0.f;
#pragma unroll
        for (int w = 0; w < 8; w++) { ts += red[w * 16 + tid]; tq += red[128 + w * 16 + tid]; }
        float mean = ts * (1.f / 256.f);
        float rstd = rsqrtf(tq * (1.f / 256.f) - mean * mean + EPSLN);
        stt[tid] = rstd; stt[16 + tid] = -mean * rstd;
    }
    __syncthreads();
    float Al = stt[quad], Bl = stt[16 + quad];
    float Ah = stt[quad + 8], Bh = stt[16 + quad + 8];
#pragma unroll
    for (int t = 0; t < 4; t++) {
        int cb = warp * 32 + t * 8 + q * 2;
        float2 gg = *(float2*)(CST + 512 + cb);
        float2 nn = *(float2*)(CST + 768 + cb);
        float kv0 = (v[t][0] * Al + Bl) * gg.x + nn.x;
        float kv1 = (v[t][1] * Al + Bl) * gg.y + nn.y;
        float kv2 = (v[t][2] * Ah + Bh) * gg.x + nn.x;
        float kv3 = (v[t][3] * Ah + Bh) * gg.y + nn.y;
        if (ST == 0) {
            const float c3 = DT * (1.f / 3.f);
            k1_[t][0] = kv0; k1_[t][1] = kv1; k1_[t][2] = kv2; k1_[t][3] = kv3;
            ar_[t][0] = ys_[t][0] + c3 * kv0; ar_[t][1] = ys_[t][1] + c3 * kv1;
            ar_[t][2] = ys_[t][2] + c3 * kv2; ar_[t][3] = ys_[t][3] + c3 * kv3;
        } else if (ST == 1) {
            k2_[t][0] = kv0; k2_[t][1] = kv1; k2_[t][2] = kv2; k2_[t][3] = kv3;
            ar_[t][0] = ys_[t][0] + DT * (kv0 - (1.f / 3.f) * k1_[t][0]);
            ar_[t][1] = ys_[t][1] + DT * (kv1 - (1.f / 3.f) * k1_[t][1]);
            ar_[t][2] = ys_[t][2] + DT * (kv2 - (1.f / 3.f) * k1_[t][2]);
            ar_[t][3] = ys_[t][3] + DT * (kv3 - (1.f / 3.f) * k1_[t][3]);
        } else if (ST == 2) {
            k3_[t][0] = kv0; k3_[t][1] = kv1; k3_[t][2] = kv2; k3_[t][3] = kv3;
            ar_[t][0] = ys_[t][0] + DT * (k1_[t][0] - k2_[t][0] + kv0);
            ar_[t][1] = ys_[t][1] + DT * (k1_[t][1] - k2_[t][1] + kv1);
            ar_[t][2] = ys_[t][2] + DT * (k1_[t][2] - k2_[t][2] + kv2);
            ar_[t][3] = ys_[t][3] + DT * (k1_[t][3] - k2_[t][3] + kv3);
        } else {
            ys_[t][0] += (DT * 0.125f) * (k1_[t][0] + 3.f * (k2_[t][0] + k3_[t][0]) + kv0);
            ys_[t][1] += (DT * 0.125f) * (k1_[t][1] + 3.f * (k2_[t][1] + k3_[t][1]) + kv1);
            ys_[t][2] += (DT * 0.125f) * (k1_[t][2] + 3.f * (k2_[t][2] + k3_[t][2]) + kv2);
            ys_[t][3] += (DT * 0.125f) * (k1_[t][3] + 3.f * (k2_[t][3] + k3_[t][3]) + kv3);
        }
        const float (&src)[4] = (ST < 3) ? ar_[t] : ys_[t];
        sts1u(sbase + astb2(quad, cb), f2bf2(src[0], src[1]));
        sts1u(sbase + astb2(quad + 8, cb), f2bf2(src[2], src[3]));
    }
}

__global__ void __launch_bounds__(256, 1)
ode_mma_kernel(const int* __restrict__ lead, const int* __restrict__ nsp,
               const float* __restrict__ bl1, const float* __restrict__ bl2,
               const float* __restrict__ gn, const float* __restrict__ bn,
               const float* __restrict__ g2, const float* __restrict__ b2,
               float* __restrict__ out) {
    extern __shared__ __align__(16) float smF[];
    uint32_t sbase;
    asm("{ .reg .u64 t; cvta.to.shared.u64 t, %1; cvt.u32.u64 %0, t; }"
        : "=r"(sbase) : "l"((const void*)smF));
    int tid = threadIdx.x, warp = tid >> 5, lane = tid & 31;
    int quad = lane >> 2, q = lane & 3;
    int r0 = blockIdx.x * 16;
    int steps = lead[r0 >> 8];
    int ns = nsp ? nsp[0] : 50;
    if (steps > ns) steps = ns;
    if (steps < 0) steps = 0;

    // load W1 resident (one cp.async group)
#pragma unroll
    for (int i = 0; i < 32; i++) {
        int off = (tid + i * 256) * 16;
        cp_async16(sbase + OFF_W1R + off, (const char*)g_wt1 + off);
    }
    cp_commit();

    float* CST = smF + OFF_CST / 4;
    for (int i = tid; i < 256; i += 256) {
        CST[i] = bl1[i]; CST[256 + i] = bl2[i];
        CST[512 + i] = gn[i]; CST[768 + i] = bn[i];
    }

    // register-resident RK4 state (thread tile is feval-invariant)
    float ys_[4][4], ar_[4][4], k1_[4][4], k2_[4][4], k3_[4][4];
#pragma unroll
    for (int t = 0; t < 4; t++) {
        int cb = warp * 32 + t * 8 + q * 2;
        float2 lo = *(const float2*)(g_x1 + (r0 + quad) * 256 + cb);
        float2 hi = *(const float2*)(g_x1 + (r0 + quad + 8) * 256 + cb);
        ys_[t][0] = lo.x; ys_[t][1] = lo.y; ys_[t][2] = hi.x; ys_[t][3] = hi.y;
        sts1u(sbase + astb2(quad, cb), f2bf2(lo.x, lo.y));
        sts1u(sbase + astb2(quad + 8, cb), f2bf2(hi.x, hi.y));
    }
    cp_wait0();
    __syncthreads();

    float acc[4][4];
    for (int s = 0; s < steps; s++) {
#pragma unroll 1
        for (int st = 0; st < 4; st++) {
            // prime W2 blocks 0,1 (overlaps with GEMM1)
            prefW2pair(sbase, 0, tid);
            run_gemm1(sbase, acc, warp, lane);
            __syncthreads();
            // epi1: h1 = relu(acc + bl1) -> A-stage (bf16)
#pragma unroll
            for (int t = 0; t < 4; t++) {
                int cb = warp * 32 + t * 8 + q * 2;
                float2 bias = *(float2*)(CST + cb);
                sts1u(sbase + astb2(quad, cb),
                      f2bf2(fmaxf(acc[t][0] + bias.x, 0.f), fmaxf(acc[t][1] + bias.y, 0.f)));
                sts1u(sbase + astb2(quad + 8, cb),
                      f2bf2(fmaxf(acc[t][2] + bias.x, 0.f), fmaxf(acc[t][3] + bias.y, 0.f)));
            }
            // GEMM2's internal first wait+sync publishes epi1 stores
            run_gemm2(sbase, acc, warp, lane, tid);
            if (st == 0)      epi2<0>(smF, sbase, acc, ys_, ar_, k1_, k2_, k3_, warp, lane, tid);
            else if (st == 1) epi2<1>(smF, sbase, acc, ys_, ar_, k1_, k2_, k3_, warp, lane, tid);
            else if (st == 2) epi2<2>(smF, sbase, acc, ys_, ar_, k1_, k2_, k3_, warp, lane, tid);
            else              epi2<3>(smF, sbase, acc, ys_, ar_, k1_, k2_, k3_, warp, lane, tid);
            __syncthreads();
        }
    }
    cp_wait0();

    // ---- fused output LN from register state: out = LN(x1 + ys; g2, b2) ----
    {
        float* red = smF + OFF_RED / 4;
        float* stt = smF + OFF_STAT / 4;
        float v[4][4];
        float sl = 0.f, sh = 0.f, ql = 0.f, qh = 0.f;
#pragma unroll
        for (int t = 0; t < 4; t++) {
            int cb = warp * 32 + t * 8 + q * 2;
            float2 lo = *(const float2*)(g_x1 + (r0 + quad) * 256 + cb);
            float2 hi = *(const float2*)(g_x1 + (r0 + quad + 8) * 256 + cb);
            float v00 = ys_[t][0] + lo.x, v01 = ys_[t][1] + lo.y;
            float v10 = ys_[t][2] + hi.x, v11 = ys_[t][3] + hi.y;
            v[t][0] = v00; v[t][1] = v01; v[t][2] = v10; v[t][3] = v11;
            sl += v00 + v01; ql += v00 * v00 + v01 * v01;
            sh += v10 + v11; qh += v10 * v10 + v11 * v11;
        }
#pragma unroll
        for (int o = 1; o < 4; o <<= 1) {
            sl += __shfl_xor_sync(0xffffffffu, sl, o);
            sh += __shfl_xor_sync(0xffffffffu, sh, o);
            ql += __shfl_xor_sync(0xffffffffu, ql, o);
            qh += __shfl_xor_sync(0xffffffffu, qh, o);
        }
        if (q == 0) {
            red[warp * 16 + quad] = sl;
            red[warp * 16 + quad + 8] = sh;
            red[128 + warp * 16 + quad] = ql;
            red[128 + warp * 16 + quad + 8] = qh;
        }
        __syncthreads();
        if (tid < 16) {
            float ts = 0.f, tq = 0.f;
#pragma unroll
            for (int w = 0; w < 8; w++) { ts += red[w * 16 + tid]; tq += red[128 + w * 16 + tid]; }
            float mean = ts * (1.f / 256.f);
            float rstd = rsqrtf(tq * (1.f / 256.f) - mean * mean + EPSLN);
            stt[tid] = rstd; stt[16 + tid] = -mean * rstd;
        }
        __syncthreads();
        float Al = stt[quad], Bl = stt[16 + quad];
        float Ah = stt[quad + 8], Bh = stt[16 + quad + 8];
#pragma unroll
        for (int t = 0; t < 4; t++) {
            int cb = warp * 32 + t * 8 + q * 2;
            float2 gg = *(const float2*)(g2 + cb);
            float2 nn = *(const float2*)(b2 + cb);
            float2 olo, ohi;
            olo.x = (v[t][0] * Al + Bl) * gg.x + nn.x;
            olo.y = (v[t][1] * Al + Bl) * gg.y + nn.y;
            ohi.x = (v[t][2] * Ah + Bh) * gg.x + nn.x;
            ohi.y = (v[t][3] * Ah + Bh) * gg.y + nn.y;
            *(float2*)(out + (r0 + quad) * 256 + cb) = olo;
            *(float2*)(out + (r0 + quad + 8) * 256 + cb) = ohi;
        }
    }
}

// ---------------------------------------------------------------------------
// Launch
// ---------------------------------------------------------------------------
extern "C" void kernel_launch(void* const* d_in, const int* in_sizes, int n_in,
                              void* d_out, int out_size) {
    const float* x    = (const float*)d_in[0];
    const float* wqkv = (const float*)d_in[1];
    const float* bqkv = (const float*)d_in[2];
    const float* wo   = (const float*)d_in[3];
    const float* bo   = (const float*)d_in[4];
    const float* g1   = (const float*)d_in[5];
    const float* b1   = (const float*)d_in[6];
    const float* g2   = (const float*)d_in[7];
    const float* b2   = (const float*)d_in[8];
    const float* wl1  = (const float*)d_in[9];
    const float* bl1  = (const float*)d_in[10];
    const float* wl2  = (const float*)d_in[11];
    const float* bl2  = (const float*)d_in[12];
    const float* gn   = (const float*)d_in[13];
    const float* bn   = (const float*)d_in[14];
    const int* lead   = (const int*)d_in[15];
    const int* nsteps = (n_in > 16) ? (const int*)d_in[16] : nullptr;
    float* out = (float*)d_out;

    cudaFuncSetAttribute(attn_kernel, cudaFuncAttributeMaxDynamicSharedMemorySize, ATTN_SMEM);
    cudaFuncSetAttribute(ode_mma_kernel, cudaFuncAttributeMaxDynamicSharedMemorySize, ODE_SMEM);
    cudaFuncSetAttribute(qkv_mma_kernel, cudaFuncAttributeMaxDynamicSharedMemorySize, QKV_SMEM);
    cudaFuncSetAttribute(proj_mma_kernel, cudaFuncAttributeMaxDynamicSharedMemorySize, PROJ_SMEM);

    prep_all_kernel<<<256, 256>>>(wl1, wl2, wqkv, wo);
    qkv_mma_kernel<<<dim3(128, 3), 256, QKV_SMEM>>>(x, bqkv);
    attn_kernel<<<128, 256, ATTN_SMEM>>>();
    proj_mma_kernel<<<128, 256, PROJ_SMEM>>>(x, bo, g1, b1);
    ode_mma_kernel<<<128, 256, ODE_SMEM>>>(lead, nsteps, bl1, bl2, gn, bn, g2, b2, out);
}